// round 12
// baseline (speedup 1.0000x reference)
#include <cuda_runtime.h>
#include <math.h>
#include <stdint.h>

#define Bb 64
#define LL 512
#define DD 512

// ----------------------------- scratch ---------------------------------------
// proj tiles (8KB) in EXACT mma_block A-fragment order, compact-M rows
__device__ uint32_t g_projb[(size_t)Bb * 4 * 16 * 2048];
// W^T tiles (8KB) in EXACT mma_block B-fragment order
__device__ uint32_t g_wtb2[4 * 16 * 2048];
__device__ float g_mt[Bb * LL];
__device__ float g_mf[Bb * LL];
__device__ int   g_idx_t[Bb * LL];
__device__ int   g_idx_f[Bb * LL];
__device__ int   g_cnt_t[Bb];
__device__ int   g_cnt_f[Bb];
__device__ float g_rowmax[Bb * LL];
__device__ float g_colmax[Bb * LL];
__device__ float g_alpha_t[Bb * LL];
__device__ float g_alpha_f[Bb * LL];
__device__ int   g_mask_fmt;

// ----------------------------- helpers ---------------------------------------
__device__ __forceinline__ uint32_t bf16x2_pack(float lo, float hi) {
    uint32_t r;
    asm("cvt.rn.bf16x2.f32 %0, %1, %2;" : "=r"(r) : "f"(hi), "f"(lo));
    return r;
}

__device__ __forceinline__ void mma_bf16(float* c, const uint32_t* a, const uint32_t* b) {
    asm volatile(
        "mma.sync.aligned.m16n8k16.row.col.f32.bf16.bf16.f32 "
        "{%0,%1,%2,%3}, {%4,%5,%6,%7}, {%8,%9}, {%0,%1,%2,%3};\n"
        : "+f"(c[0]), "+f"(c[1]), "+f"(c[2]), "+f"(c[3])
        : "r"(a[0]), "r"(a[1]), "r"(a[2]), "r"(a[3]), "r"(b[0]), "r"(b[1]));
}

#define CP_ASYNC16(sm_u32, gptr) \
    asm volatile("cp.async.cg.shared.global [%0], [%1], 16;" \
                 :: "r"(sm_u32), "l"(gptr) : "memory")
#define CP_COMMIT() asm volatile("cp.async.commit_group;" ::: "memory")
#define CP_WAIT1()  asm volatile("cp.async.wait_group 1;" ::: "memory")
#define CP_WAIT0()  asm volatile("cp.async.wait_group 0;" ::: "memory")

__device__ __forceinline__ void atomicMaxF(float* a, float v) {
    if (v >= 0.0f) atomicMax((int*)a, __float_as_int(v));
    else           atomicMin((unsigned int*)a, __float_as_uint(v));
}

__device__ __forceinline__ float load_mask(const void* p, int i, int fmt) {
    if (fmt == 0) return ((const int*)p)[i] ? 1.0f : 0.0f;
    if (fmt == 1) return ((const float*)p)[i];
    return ((const unsigned char*)p)[i] ? 1.0f : 0.0f;
}

// ---- bf16 fragment-layout writers (mapping validated R5-R11) -------------------
__device__ __forceinline__ void stA_nm(uint32_t* dst, int row, int kk, int p0, float4 v) {
    uint32_t w0 = bf16x2_pack(v.x, v.y);
    uint32_t w1 = bf16x2_pack(v.z, v.w);
    const int base = (((row >> 4) * 2 + kk) << 7) + ((row & 15) >> 3);
    const int rl = (row & 7) * 4;
    int lane = rl + (p0 & 3), phys = lane ^ (lane >> 3);
    dst[base + phys * 4 + ((p0 >> 2) << 1)] = w0;
    int p = p0 + 1;
    lane = rl + (p & 3); phys = lane ^ (lane >> 3);
    dst[base + phys * 4 + ((p >> 2) << 1)] = w1;
}

__device__ __forceinline__ void stB_nm(uint32_t* dst, int col, int kk, int p0, float4 v) {
    uint32_t w0 = bf16x2_pack(v.x, v.y);
    uint32_t w1 = bf16x2_pack(v.z, v.w);
    const int base = (((col >> 3) * 2 + kk) << 6);
    const int rl = (col & 7) * 4;
    int lane = rl + (p0 & 3), phys = lane ^ (lane >> 3);
    dst[base + phys * 2 + (p0 >> 2)] = w0;
    int p = p0 + 1;
    lane = rl + (p & 3); phys = lane ^ (lane >> 3);
    dst[base + phys * 2 + (p >> 2)] = w1;
}

__device__ __forceinline__ float4 zmask(float4 v, bool pred) {
    if (!pred) { v.x = 0.f; v.y = 0.f; v.z = 0.f; v.w = 0.f; }
    return v;
}

// ---- 32x32 warp-tile MMA block (acc[2][4][4]) -----------------------------------
__device__ __forceinline__ void mma_block32(const uint32_t* Asb, const uint32_t* Bsb,
                                            int kk, int wm, int wn, int physL,
                                            float acc[2][4][4]) {
    uint4 af[2]; uint2 bfv[4];
#pragma unroll
    for (int mt = 0; mt < 2; mt++)
        af[mt] = *(const uint4*)&Asb[(((wm * 2 + mt) * 2 + kk) << 7) + physL * 4];
#pragma unroll
    for (int nt = 0; nt < 4; nt++)
        bfv[nt] = *(const uint2*)&Bsb[(((wn * 4 + nt) * 2 + kk) << 6) + physL * 2];
#pragma unroll
    for (int mt = 0; mt < 2; mt++)
#pragma unroll
        for (int nt = 0; nt < 4; nt++)
            mma_bf16(acc[mt][nt], (const uint32_t*)&af[mt], (const uint32_t*)&bfv[nt]);
}

// ----------------------------- small kernels ----------------------------------
__global__ void detect_kernel(const unsigned int* m) {
    int lane = threadIdx.x;
    bool i32 = true, f32 = true;
    for (int i = lane; i < 256; i += 32) {
        unsigned int w = m[i];
        i32 = i32 && (w <= 1u);
        f32 = f32 && (w == 0u || w == 0x3F800000u);
    }
    i32 = __all_sync(0xffffffffu, i32);
    f32 = __all_sync(0xffffffffu, f32);
    if (lane == 0) g_mask_fmt = i32 ? 0 : (f32 ? 1 : 2);
}

__global__ void compact_kernel(const void* mt, const void* mf) {
    const int x = blockIdx.x;
    const int b = x >> 1;
    const bool isF = x & 1;
    const int tid = threadIdx.x;
    const int fmt = g_mask_fmt;
    const float mv = load_mask(isF ? mf : mt, b * LL + tid, fmt);
    (isF ? g_mf : g_mt)[b * LL + tid] = mv;
    (isF ? g_colmax : g_rowmax)[b * LL + tid] = __int_as_float(0xff800000);

    const bool on = (mv != 0.0f);
    const unsigned bal = __ballot_sync(0xffffffffu, on);
    __shared__ int wsum[16];
    __shared__ int wbase[16];
    const int wid = tid >> 5, lane = tid & 31;
    if (lane == 0) wsum[wid] = __popc(bal);
    __syncthreads();
    if (tid == 0) {
        int s = 0;
        for (int i = 0; i < 16; i++) { wbase[i] = s; s += wsum[i]; }
        if (isF) g_cnt_f[b] = s; else g_cnt_t[b] = s;
    }
    __syncthreads();
    if (on) {
        int pos = wbase[wid] + __popc(bal & ((1u << lane) - 1u));
        (isF ? g_idx_f : g_idx_t)[b * LL + pos] = tid;
    }
}

__global__ void pack_w(const float* __restrict__ W) {
    const int p = blockIdx.x;
    const int n = threadIdx.x;
    const int k0 = p * 2;
    float lo = W[(size_t)k0 * DD + n];
    float hi = W[(size_t)(k0 + 1) * DD + n];
    const int nt = n >> 7, col = n & 127;
    const int kt = p >> 4, kk = (p >> 3) & 1, pl = p & 7;
    const int lane_v = (col & 7) * 4 + (pl & 3);
    const int phys = lane_v ^ (lane_v >> 3);
    const int idx = (nt * 16 + kt) * 2048 +
                    (((col >> 3) * 2 + kk) << 6) + phys * 2 + (pl >> 2);
    g_wtb2[idx] = bf16x2_pack(lo, hi);
}

// ----------------------------- GEMM 0: proj = compact(t) @ W^T ------------------
// 512 threads, warp tile 32x32. A via registers (2-stage); B via cp.async (3-stage).
__global__ void __launch_bounds__(512, 2) gemm0_kernel(const float* __restrict__ T)
{
    __shared__ __align__(16) uint32_t As[2][2048];
    __shared__ __align__(16) uint32_t Bs[3][2048];

    const int tid  = threadIdx.x;
    const int lane = tid & 31;
    const int wid  = tid >> 5;          // 0..15
    const int wm   = wid & 3;           // 4 M groups (32 rows each)
    const int wn   = wid >> 2;          // 4 N groups (32 cols each)
    const int b  = blockIdx.z;
    const int l0 = blockIdx.y * 128;
    const int nt_tile = blockIdx.x;

    const int cnt = g_cnt_t[b];
    if (l0 >= cnt) return;

    const int gr = tid >> 2;            // 0..127, one row per thread
    const int gc = (tid & 3) * 4;       // k offset within 16-k chunk
    const int p0 = gc >> 1;
    const int physL = lane ^ (lane >> 3);

    const int j0 = l0 + gr;
    const bool pr0 = (j0 < cnt);
    const int r0 = pr0 ? g_idx_t[b * LL + j0] : 0;

    const float* Ab0 = T + ((size_t)b * LL + r0) * DD + gc;
    const uint32_t* Wtile = g_wtb2 + (size_t)nt_tile * 16 * 2048 + tid * 4;

    uint32_t bs_u32[3];
#pragma unroll
    for (int s = 0; s < 3; s++)
        bs_u32[s] = (uint32_t)__cvta_generic_to_shared(&Bs[s][tid * 4]);

    float acc[2][4][4];
#pragma unroll
    for (int i = 0; i < 2; i++)
#pragma unroll
        for (int j = 0; j < 4; j++)
#pragma unroll
            for (int q = 0; q < 4; q++) acc[i][j][q] = 0.0f;

    // prologue
    CP_ASYNC16(bs_u32[0], Wtile);
    CP_COMMIT();
    CP_ASYNC16(bs_u32[1], Wtile + 2048);
    CP_COMMIT();
    {
        float4 v;
        v = zmask(*(const float4*)(Ab0), pr0);      stA_nm(As[0], gr, 0, p0, v);
        v = zmask(*(const float4*)(Ab0 + 16), pr0); stA_nm(As[0], gr, 1, p0, v);
    }
    CP_WAIT1();
    __syncthreads();

    for (int kt = 0; kt < 16; kt++) {
        const int buf2 = kt & 1;
        const int buf3 = kt % 3;
        const bool more = (kt + 1 < 16);

        float4 va0, va1;
        if (more) {
            const int K0 = (kt + 1) * 32;
            va0 = zmask(*(const float4*)(Ab0 + K0), pr0);
            va1 = zmask(*(const float4*)(Ab0 + K0 + 16), pr0);
        }
        if (kt + 2 < 16) {
            const int s3 = (kt + 2) % 3;
            CP_ASYNC16(bs_u32[s3], Wtile + (size_t)(kt + 2) * 2048);
            CP_COMMIT();
        }

        mma_block32(As[buf2], Bs[buf3], 0, wm, wn, physL, acc);

        if (more) {
            stA_nm(As[buf2 ^ 1], gr, 0, p0, va0);
            stA_nm(As[buf2 ^ 1], gr, 1, p0, va1);
        }

        mma_block32(As[buf2], Bs[buf3], 1, wm, wn, physL, acc);

        if (more) {
            if (kt + 2 < 16) { CP_WAIT1(); } else { CP_WAIT0(); }
            __syncthreads();
        }
    }

    // epilogue: proj tiles in EXACT mma_block A-fragment layout (validated R9/R11)
    const int lx = lane & 3, ly = lane >> 2;
    uint32_t* Ptile = g_projb + ((size_t)b * 4 + blockIdx.y) * 16 * 2048;
#pragma unroll
    for (int mt = 0; mt < 2; mt++) {
        const int mtile = wm * 2 + mt;
#pragma unroll
        for (int nt = 0; nt < 4; nt++) {
            const int c = nt_tile * 128 + (wn * 4 + nt) * 8 + 2 * lx;
            const int kp_g = c >> 1;
            const int kt1 = kp_g >> 4;
            const int kk1 = (kp_g >> 3) & 1;
            const int kp  = kp_g & 7;
            const int lane_v = ly * 4 + (kp & 3);
            const int phys = lane_v ^ (lane_v >> 3);
            const int si = (kp >= 4) ? 2 : 0;
            const int idx = kt1 * 2048 + (((mtile * 2 + kk1) << 7)) + phys * 4 + si;
            uint2 w;
            w.x = bf16x2_pack(acc[mt][nt][0], acc[mt][nt][1]);
            w.y = bf16x2_pack(acc[mt][nt][2], acc[mt][nt][3]);
            *(uint2*)&Ptile[idx] = w;
        }
    }
}

// ------------- GEMM 1: M = proj(compact) @ compact(f)^T, fused max --------------
// 512 threads, warp tile 32x32. A via cp.async (3-stage); B via registers (2-stage).
__global__ void __launch_bounds__(512, 2) gemm1_kernel(const float* __restrict__ F)
{
    __shared__ __align__(16) uint32_t As[3][2048];
    __shared__ __align__(16) uint32_t Bs[2][2048];
    __shared__ float s_rmax[128];
    __shared__ float s_cmax[128];

    const int tid  = threadIdx.x;
    const int lane = tid & 31;
    const int wid  = tid >> 5;
    const int wm   = wid & 3;
    const int wn   = wid >> 2;
    const int b  = blockIdx.z;
    const int l0 = blockIdx.y * 128;
    const int n0 = blockIdx.x * 128;

    const int cnt_t = g_cnt_t[b];
    const int cnt_f = g_cnt_f[b];
    if (l0 >= cnt_t || n0 >= cnt_f) return;

    const int gr = tid >> 2;
    const int gc = (tid & 3) * 4;
    const int p0 = gc >> 1;
    const int physL = lane ^ (lane >> 3);
    const float NINF = __int_as_float(0xff800000);

    const int j0 = n0 + gr;
    const bool pr0 = (j0 < cnt_f);
    const int c0 = pr0 ? g_idx_f[b * LL + j0] : 0;

    if (tid < 128) { s_rmax[tid] = NINF; s_cmax[tid] = NINF; }

    const uint32_t* Ptile = g_projb + ((size_t)b * 4 + blockIdx.y) * 16 * 2048 + tid * 4;
    const float* Fb0 = F + ((size_t)b * LL + c0) * DD + gc;

    uint32_t as_u32[3];
#pragma unroll
    for (int s = 0; s < 3; s++)
        as_u32[s] = (uint32_t)__cvta_generic_to_shared(&As[s][tid * 4]);

    float acc[2][4][4];
#pragma unroll
    for (int i = 0; i < 2; i++)
#pragma unroll
        for (int j = 0; j < 4; j++)
#pragma unroll
            for (int q = 0; q < 4; q++) acc[i][j][q] = 0.0f;

    // prologue
    CP_ASYNC16(as_u32[0], Ptile);
    CP_COMMIT();
    CP_ASYNC16(as_u32[1], Ptile + 2048);
    CP_COMMIT();
    {
        float4 v;
        v = zmask(*(const float4*)(Fb0), pr0);      stB_nm(Bs[0], gr, 0, p0, v);
        v = zmask(*(const float4*)(Fb0 + 16), pr0); stB_nm(Bs[0], gr, 1, p0, v);
    }
    CP_WAIT1();
    __syncthreads();

    for (int kt = 0; kt < 16; kt++) {
        const int buf2 = kt & 1;
        const int buf3 = kt % 3;
        const bool more = (kt + 1 < 16);

        float4 vb0, vb1;
        if (more) {
            const int K0 = (kt + 1) * 32;
            vb0 = zmask(*(const float4*)(Fb0 + K0), pr0);
            vb1 = zmask(*(const float4*)(Fb0 + K0 + 16), pr0);
        }
        if (kt + 2 < 16) {
            const int s3 = (kt + 2) % 3;
            CP_ASYNC16(as_u32[s3], Ptile + (size_t)(kt + 2) * 2048);
            CP_COMMIT();
        }

        mma_block32(As[buf3], Bs[buf2], 0, wm, wn, physL, acc);

        if (more) {
            stB_nm(Bs[buf2 ^ 1], gr, 0, p0, vb0);
            stB_nm(Bs[buf2 ^ 1], gr, 1, p0, vb1);
        }

        mma_block32(As[buf3], Bs[buf2], 1, wm, wn, physL, acc);

        if (more) {
            if (kt + 2 < 16) { CP_WAIT1(); } else { CP_WAIT0(); }
            __syncthreads();
        }
    }

    // fused row/col max epilogue with index scatter
    __syncthreads();
    const int lx = lane & 3, ly = lane >> 2;
#pragma unroll
    for (int mt = 0; mt < 2; mt++) {
#pragma unroll
        for (int h = 0; h < 2; h++) {
            float v = NINF;
#pragma unroll
            for (int nt = 0; nt < 4; nt++)
                v = fmaxf(v, fmaxf(acc[mt][nt][2 * h], acc[mt][nt][2 * h + 1]));
            v = fmaxf(v, __shfl_xor_sync(0xffffffffu, v, 1));
            v = fmaxf(v, __shfl_xor_sync(0xffffffffu, v, 2));
            if (lx == 0) atomicMaxF(&s_rmax[(wm * 2 + mt) * 16 + ly + h * 8], v);
        }
    }
#pragma unroll
    for (int nt = 0; nt < 4; nt++) {
#pragma unroll
        for (int j = 0; j < 2; j++) {
            float v = NINF;
#pragma unroll
            for (int mt = 0; mt < 2; mt++)
                v = fmaxf(v, fmaxf(acc[mt][nt][j], acc[mt][nt][2 + j]));
            v = fmaxf(v, __shfl_xor_sync(0xffffffffu, v, 4));
            v = fmaxf(v, __shfl_xor_sync(0xffffffffu, v, 8));
            v = fmaxf(v, __shfl_xor_sync(0xffffffffu, v, 16));
            if (lane < 4) atomicMaxF(&s_cmax[(wn * 4 + nt) * 8 + 2 * lane + j], v);
        }
    }
    __syncthreads();
    if (tid < 128) {
        const int jr = l0 + tid;
        if (jr < cnt_t)
            atomicMaxF(&g_rowmax[b * LL + g_idx_t[b * LL + jr]], s_rmax[tid]);
        const int jc = n0 + tid;
        if (jc < cnt_f)
            atomicMaxF(&g_colmax[b * LL + g_idx_f[b * LL + jc]], s_cmax[tid]);
    }
}

// ----------------------------- softmax ----------------------------------------
__global__ void softmax_kernel() {
    const int idx = blockIdx.x;
    const bool isF = idx >= Bb;
    const int b = isF ? idx - Bb : idx;
    const float* mx = isF ? (g_colmax + b * LL) : (g_rowmax + b * LL);
    const float* mk = isF ? (g_mf + b * LL) : (g_mt + b * LL);
    float* out = isF ? (g_alpha_f + b * LL) : (g_alpha_t + b * LL);
    const int cnt_other = isF ? g_cnt_t[b] : g_cnt_f[b];

    const int tid = threadIdx.x;
    int i0 = tid, i1 = tid + 256;
    float m0v = mk[i0], m1v = mk[i1];
    float x0 = mx[i0], x1 = mx[i1];
    if (cnt_other < 512) { x0 = fmaxf(x0, 0.0f); x1 = fmaxf(x1, 0.0f); }
    float v0 = tanhf(x0) + (m0v - 1.0f) * 1000000.0f;
    float v1 = tanhf(x1) + (m1v - 1.0f) * 1000000.0f;

    __shared__ float red[256];
    red[tid] = fmaxf(v0, v1);
    __syncthreads();
    for (int s = 128; s > 0; s >>= 1) {
        if (tid < s) red[tid] = fmaxf(red[tid], red[tid + s]);
        __syncthreads();
    }
    float vm = red[0];
    __syncthreads();

    float e0 = expf(v0 - vm);
    float e1 = expf(v1 - vm);
    red[tid] = e0 + e1;
    __syncthreads();
    for (int s = 128; s > 0; s >>= 1) {
        if (tid < s) red[tid] += red[tid + s];
        __syncthreads();
    }
    float inv = 1.0f / red[0];
    out[i0] = e0 * inv * m0v;
    out[i1] = e1 * inv * m1v;
}

// ----------------------------- combine (compact) --------------------------------
__global__ void combine_kernel(const float* __restrict__ T,
                               const float* __restrict__ F,
                               float* __restrict__ out)
{
    __shared__ float red[1024];
    const int b = blockIdx.y;
    const int dl = threadIdx.x & 127;
    const int chunk = threadIdx.x >> 7;           // 0..7
    const int d = blockIdx.x * 128 + dl;
    const int* it  = g_idx_t + b * LL;
    const int* ifx = g_idx_f + b * LL;
    const int ct = g_cnt_t[b], cf = g_cnt_f[b];
    const float* at = g_alpha_t + b * LL;
    const float* af = g_alpha_f + b * LL;
    const float* tp = T + (size_t)b * LL * DD + d;
    const float* fp = F + (size_t)b * LL * DD + d;
    const int jb = chunk * 64;

    float a0 = 0.f, a1 = 0.f, a2 = 0.f, a3 = 0.f;
    {
        const int je = min(jb + 64, ct);
        int j = jb;
        for (; j + 4 <= je; j += 4) {
            int l0 = it[j], l1 = it[j + 1], l2 = it[j + 2], l3 = it[j + 3];
            a0 = fmaf(at[l0], tp[(size_t)l0 * DD], a0);
            a1 = fmaf(at[l1], tp[(size_t)l1 * DD], a1);
            a2 = fmaf(at[l2], tp[(size_t)l2 * DD], a2);
            a3 = fmaf(at[l3], tp[(size_t)l3 * DD], a3);
        }
        for (; j < je; j++) {
            int l = it[j];
            a0 = fmaf(at[l], tp[(size_t)l * DD], a0);
        }
    }
    {
        const int je = min(jb + 64, cf);
        int j = jb;
        for (; j + 4 <= je; j += 4) {
            int l0 = ifx[j], l1 = ifx[j + 1], l2 = ifx[j + 2], l3 = ifx[j + 3];
            a0 = fmaf(af[l0], fp[(size_t)l0 * DD], a0);
            a1 = fmaf(af[l1], fp[(size_t)l1 * DD], a1);
            a2 = fmaf(af[l2], fp[(size_t)l2 * DD], a2);
            a3 = fmaf(af[l3], fp[(size_t)l3 * DD], a3);
        }
        for (; j < je; j++) {
            int l = ifx[j];
            a0 = fmaf(af[l], fp[(size_t)l * DD], a0);
        }
    }
    red[threadIdx.x] = (a0 + a1) + (a2 + a3);
    __syncthreads();
    if (chunk == 0) {
        float s = 0.f;
#pragma unroll
        for (int i = 0; i < 8; i++) s += red[dl + 128 * i];
        out[b * DD + d] = s;
    }
}

// ----------------------------- launch -------------------------------------------
extern "C" void kernel_launch(void* const* d_in, const int* in_sizes, int n_in,
                              void* d_out, int out_size)
{
    const float* t  = (const float*)d_in[0];
    const float* f  = (const float*)d_in[1];
    const void*  mt = d_in[2];
    const void*  mf = d_in[3];
    const float* w  = (const float*)d_in[4];
    float* out = (float*)d_out;

    detect_kernel<<<1, 32>>>((const unsigned int*)mt);
    compact_kernel<<<2 * Bb, 512>>>(mt, mf);
    pack_w<<<256, 512>>>(w);
    gemm0_kernel<<<dim3(4, 4, Bb), 512>>>(t);
    gemm1_kernel<<<dim3(4, 4, Bb), 512>>>(f);
    softmax_kernel<<<2 * Bb, 256>>>();
    combine_kernel<<<dim3(4, Bb), 1024>>>(t, f, out);
}

// round 13
// speedup vs baseline: 1.2126x; 1.2126x over previous
#include <cuda_runtime.h>
#include <math.h>
#include <stdint.h>

#define Bb 64
#define LL 512
#define DD 512

// ----------------------------- scratch ---------------------------------------
// proj tiles (8KB) in EXACT mma_block A-fragment order, compact-M rows
__device__ uint32_t g_projb[(size_t)Bb * 4 * 16 * 2048];
// W^T tiles (8KB) in EXACT mma_block B-fragment order
__device__ uint32_t g_wtb2[4 * 16 * 2048];
__device__ float g_mt[Bb * LL];
__device__ float g_mf[Bb * LL];
__device__ int   g_idx_t[Bb * LL];
__device__ int   g_idx_f[Bb * LL];
__device__ int   g_cnt_t[Bb];
__device__ int   g_cnt_f[Bb];
__device__ float g_rowmax[Bb * LL];
__device__ float g_colmax[Bb * LL];
__device__ float g_alpha_t[Bb * LL];
__device__ float g_alpha_f[Bb * LL];
__device__ int   g_mask_fmt;

// ----------------------------- helpers ---------------------------------------
__device__ __forceinline__ uint32_t bf16x2_pack(float lo, float hi) {
    uint32_t r;
    asm("cvt.rn.bf16x2.f32 %0, %1, %2;" : "=r"(r) : "f"(hi), "f"(lo));
    return r;
}

__device__ __forceinline__ void mma_bf16(float* c, const uint32_t* a, const uint32_t* b) {
    asm volatile(
        "mma.sync.aligned.m16n8k16.row.col.f32.bf16.bf16.f32 "
        "{%0,%1,%2,%3}, {%4,%5,%6,%7}, {%8,%9}, {%0,%1,%2,%3};\n"
        : "+f"(c[0]), "+f"(c[1]), "+f"(c[2]), "+f"(c[3])
        : "r"(a[0]), "r"(a[1]), "r"(a[2]), "r"(a[3]), "r"(b[0]), "r"(b[1]));
}

#define CP_ASYNC16(sm_u32, gptr) \
    asm volatile("cp.async.cg.shared.global [%0], [%1], 16;" \
                 :: "r"(sm_u32), "l"(gptr) : "memory")
#define CP_COMMIT() asm volatile("cp.async.commit_group;" ::: "memory")
#define CP_WAIT1()  asm volatile("cp.async.wait_group 1;" ::: "memory")
#define CP_WAIT0()  asm volatile("cp.async.wait_group 0;" ::: "memory")

__device__ __forceinline__ void atomicMaxF(float* a, float v) {
    if (v >= 0.0f) atomicMax((int*)a, __float_as_int(v));
    else           atomicMin((unsigned int*)a, __float_as_uint(v));
}

__device__ __forceinline__ float load_mask(const void* p, int i, int fmt) {
    if (fmt == 0) return ((const int*)p)[i] ? 1.0f : 0.0f;
    if (fmt == 1) return ((const float*)p)[i];
    return ((const unsigned char*)p)[i] ? 1.0f : 0.0f;
}

// ---- bf16 fragment-layout writers (mapping validated R5-R11) -------------------
__device__ __forceinline__ void stA_nm(uint32_t* dst, int row, int kk, int p0, float4 v) {
    uint32_t w0 = bf16x2_pack(v.x, v.y);
    uint32_t w1 = bf16x2_pack(v.z, v.w);
    const int base = (((row >> 4) * 2 + kk) << 7) + ((row & 15) >> 3);
    const int rl = (row & 7) * 4;
    int lane = rl + (p0 & 3), phys = lane ^ (lane >> 3);
    dst[base + phys * 4 + ((p0 >> 2) << 1)] = w0;
    int p = p0 + 1;
    lane = rl + (p & 3); phys = lane ^ (lane >> 3);
    dst[base + phys * 4 + ((p >> 2) << 1)] = w1;
}

__device__ __forceinline__ void stB_nm(uint32_t* dst, int col, int kk, int p0, float4 v) {
    uint32_t w0 = bf16x2_pack(v.x, v.y);
    uint32_t w1 = bf16x2_pack(v.z, v.w);
    const int base = (((col >> 3) * 2 + kk) << 6);
    const int rl = (col & 7) * 4;
    int lane = rl + (p0 & 3), phys = lane ^ (lane >> 3);
    dst[base + phys * 2 + (p0 >> 2)] = w0;
    int p = p0 + 1;
    lane = rl + (p & 3); phys = lane ^ (lane >> 3);
    dst[base + phys * 2 + (p >> 2)] = w1;
}

__device__ __forceinline__ float4 zmask(float4 v, bool pred) {
    if (!pred) { v.x = 0.f; v.y = 0.f; v.z = 0.f; v.w = 0.f; }
    return v;
}

// ---- shared MMA block (64x32 warp tile, validated R5-R11) -----------------------
__device__ __forceinline__ void mma_block(const uint32_t* Asb, const uint32_t* Bsb,
                                          int kk, int wm, int wn, int physL,
                                          float acc[4][4][4]) {
    uint4 af[4]; uint2 bfv[4];
#pragma unroll
    for (int mt = 0; mt < 4; mt++)
        af[mt] = *(const uint4*)&Asb[(((wm * 4 + mt) * 2 + kk) << 7) + physL * 4];
#pragma unroll
    for (int nt = 0; nt < 4; nt++)
        bfv[nt] = *(const uint2*)&Bsb[(((wn * 4 + nt) * 2 + kk) << 6) + physL * 2];
#pragma unroll
    for (int mt = 0; mt < 4; mt++)
#pragma unroll
        for (int nt = 0; nt < 4; nt++)
            mma_bf16(acc[mt][nt], (const uint32_t*)&af[mt], (const uint32_t*)&bfv[nt]);
}

// ----------------------------- small kernels ----------------------------------
__global__ void detect_kernel(const unsigned int* m) {
    int lane = threadIdx.x;
    bool i32 = true, f32 = true;
    for (int i = lane; i < 256; i += 32) {
        unsigned int w = m[i];
        i32 = i32 && (w <= 1u);
        f32 = f32 && (w == 0u || w == 0x3F800000u);
    }
    i32 = __all_sync(0xffffffffu, i32);
    f32 = __all_sync(0xffffffffu, f32);
    if (lane == 0) g_mask_fmt = i32 ? 0 : (f32 ? 1 : 2);
}

__global__ void compact_kernel(const void* mt, const void* mf) {
    const int x = blockIdx.x;
    const int b = x >> 1;
    const bool isF = x & 1;
    const int tid = threadIdx.x;
    const int fmt = g_mask_fmt;
    const float mv = load_mask(isF ? mf : mt, b * LL + tid, fmt);
    (isF ? g_mf : g_mt)[b * LL + tid] = mv;
    (isF ? g_colmax : g_rowmax)[b * LL + tid] = __int_as_float(0xff800000);

    const bool on = (mv != 0.0f);
    const unsigned bal = __ballot_sync(0xffffffffu, on);
    __shared__ int wsum[16];
    __shared__ int wbase[16];
    const int wid = tid >> 5, lane = tid & 31;
    if (lane == 0) wsum[wid] = __popc(bal);
    __syncthreads();
    if (tid == 0) {
        int s = 0;
        for (int i = 0; i < 16; i++) { wbase[i] = s; s += wsum[i]; }
        if (isF) g_cnt_f[b] = s; else g_cnt_t[b] = s;
    }
    __syncthreads();
    if (on) {
        int pos = wbase[wid] + __popc(bal & ((1u << lane) - 1u));
        (isF ? g_idx_f : g_idx_t)[b * LL + pos] = tid;
    }
}

__global__ void pack_w(const float* __restrict__ W) {
    const int p = blockIdx.x;
    const int n = threadIdx.x;
    const int k0 = p * 2;
    float lo = W[(size_t)k0 * DD + n];
    float hi = W[(size_t)(k0 + 1) * DD + n];
    const int nt = n >> 7, col = n & 127;
    const int kt = p >> 4, kk = (p >> 3) & 1, pl = p & 7;
    const int lane_v = (col & 7) * 4 + (pl & 3);
    const int phys = lane_v ^ (lane_v >> 3);
    const int idx = (nt * 16 + kt) * 2048 +
                    (((col >> 3) * 2 + kk) << 6) + phys * 2 + (pl >> 2);
    g_wtb2[idx] = bf16x2_pack(lo, hi);
}

// ----------------------------- GEMM 0: proj = compact(t) @ W^T ------------------
// A (compact t rows) via registers (2-stage); B (W) via cp.async (3-stage).
__global__ void __launch_bounds__(256, 2) gemm0_kernel(const float* __restrict__ T)
{
    __shared__ __align__(16) uint32_t As[2][2048];
    __shared__ __align__(16) uint32_t Bs[3][2048];

    const int tid  = threadIdx.x;
    const int lane = tid & 31;
    const int wid  = tid >> 5;
    const int wm   = wid & 1;
    const int wn   = wid >> 1;
    const int b  = blockIdx.z;
    const int l0 = blockIdx.y * 128;
    const int nt_tile = blockIdx.x;

    const int cnt = g_cnt_t[b];
    if (l0 >= cnt) return;

    const int gr = tid >> 2;
    const int gc = (tid & 3) * 4;
    const int p0 = gc >> 1;
    const int physL = lane ^ (lane >> 3);

    const int j0 = l0 + gr, j1 = l0 + gr + 64;
    const bool pr0 = (j0 < cnt), pr1 = (j1 < cnt);
    const int r0 = pr0 ? g_idx_t[b * LL + j0] : 0;
    const int r1 = pr1 ? g_idx_t[b * LL + j1] : 0;

    const float* Ab0 = T + ((size_t)b * LL + r0) * DD + gc;
    const float* Ab1 = T + ((size_t)b * LL + r1) * DD + gc;
    const uint32_t* Wtile = g_wtb2 + (size_t)nt_tile * 16 * 2048 + tid * 8;

    uint32_t bs_u32[3];
#pragma unroll
    for (int s = 0; s < 3; s++)
        bs_u32[s] = (uint32_t)__cvta_generic_to_shared(&Bs[s][tid * 8]);

    float acc[4][4][4];
#pragma unroll
    for (int i = 0; i < 4; i++)
#pragma unroll
        for (int j = 0; j < 4; j++)
#pragma unroll
            for (int q = 0; q < 4; q++) acc[i][j][q] = 0.0f;

    // prologue
    CP_ASYNC16(bs_u32[0],      Wtile);
    CP_ASYNC16(bs_u32[0] + 16, Wtile + 4);
    CP_COMMIT();
    CP_ASYNC16(bs_u32[1],      Wtile + 2048);
    CP_ASYNC16(bs_u32[1] + 16, Wtile + 2048 + 4);
    CP_COMMIT();
    {
        float4 v;
        v = zmask(*(const float4*)(Ab0), pr0);      stA_nm(As[0], gr,      0, p0, v);
        v = zmask(*(const float4*)(Ab0 + 16), pr0); stA_nm(As[0], gr,      1, p0, v);
        v = zmask(*(const float4*)(Ab1), pr1);      stA_nm(As[0], gr + 64, 0, p0, v);
        v = zmask(*(const float4*)(Ab1 + 16), pr1); stA_nm(As[0], gr + 64, 1, p0, v);
    }
    CP_WAIT1();
    __syncthreads();

#pragma unroll
    for (int kt = 0; kt < 16; kt++) {
        const int buf2 = kt & 1;
        const int buf3 = kt % 3;
        const bool more = (kt + 1 < 16);

        float4 va0, va1, va2, va3;
        if (more) {
            const int K0 = (kt + 1) * 32;
            va0 = zmask(*(const float4*)(Ab0 + K0), pr0);
            va1 = zmask(*(const float4*)(Ab0 + K0 + 16), pr0);
            va2 = zmask(*(const float4*)(Ab1 + K0), pr1);
            va3 = zmask(*(const float4*)(Ab1 + K0 + 16), pr1);
        }
        if (kt + 2 < 16) {
            const int s3 = (kt + 2) % 3;
            CP_ASYNC16(bs_u32[s3],      Wtile + (size_t)(kt + 2) * 2048);
            CP_ASYNC16(bs_u32[s3] + 16, Wtile + (size_t)(kt + 2) * 2048 + 4);
            CP_COMMIT();
        }

        mma_block(As[buf2], Bs[buf3], 0, wm, wn, physL, acc);
        mma_block(As[buf2], Bs[buf3], 1, wm, wn, physL, acc);

        if (more) {
            stA_nm(As[buf2 ^ 1], gr,      0, p0, va0);
            stA_nm(As[buf2 ^ 1], gr,      1, p0, va1);
            stA_nm(As[buf2 ^ 1], gr + 64, 0, p0, va2);
            stA_nm(As[buf2 ^ 1], gr + 64, 1, p0, va3);
            if (kt + 2 < 16) { CP_WAIT1(); } else { CP_WAIT0(); }
            __syncthreads();
        }
    }

    // epilogue: proj tiles in EXACT mma_block A-fragment layout (validated R9/R11)
    const int lx = lane & 3, ly = lane >> 2;
    uint32_t* Ptile = g_projb + ((size_t)b * 4 + blockIdx.y) * 16 * 2048;
#pragma unroll
    for (int mt = 0; mt < 4; mt++) {
        const int mtile = wm * 4 + mt;
#pragma unroll
        for (int nt = 0; nt < 4; nt++) {
            const int c = nt_tile * 128 + wn * 32 + nt * 8 + 2 * lx;
            const int kp_g = c >> 1;
            const int kt1 = kp_g >> 4;
            const int kk1 = (kp_g >> 3) & 1;
            const int kp  = kp_g & 7;
            const int lane_v = ly * 4 + (kp & 3);
            const int phys = lane_v ^ (lane_v >> 3);
            const int si = (kp >= 4) ? 2 : 0;
            const int idx = kt1 * 2048 + (((mtile * 2 + kk1) << 7)) + phys * 4 + si;
            uint2 w;
            w.x = bf16x2_pack(acc[mt][nt][0], acc[mt][nt][1]);
            w.y = bf16x2_pack(acc[mt][nt][2], acc[mt][nt][3]);
            *(uint2*)&Ptile[idx] = w;
        }
    }
}

// ------------- GEMM 1: M = proj(compact) @ compact(f)^T, fused max --------------
// A (proj) via cp.async (3-stage); B (compact f cols) via registers (2-stage).
__global__ void __launch_bounds__(256, 2) gemm1_kernel(const float* __restrict__ F)
{
    __shared__ __align__(16) uint32_t As[3][2048];
    __shared__ __align__(16) uint32_t Bs[2][2048];
    __shared__ float s_rmax[128];
    __shared__ float s_cmax[128];

    const int tid  = threadIdx.x;
    const int lane = tid & 31;
    const int wid  = tid >> 5;
    const int wm   = wid & 1;
    const int wn   = wid >> 1;
    const int b  = blockIdx.z;
    const int l0 = blockIdx.y * 128;
    const int n0 = blockIdx.x * 128;

    const int cnt_t = g_cnt_t[b];
    const int cnt_f = g_cnt_f[b];
    if (l0 >= cnt_t || n0 >= cnt_f) return;

    const int gr = tid >> 2;
    const int gc = (tid & 3) * 4;
    const int p0 = gc >> 1;
    const int physL = lane ^ (lane >> 3);
    const float NINF = __int_as_float(0xff800000);

    const int j0 = n0 + gr, j1 = n0 + gr + 64;
    const bool pr0 = (j0 < cnt_f), pr1 = (j1 < cnt_f);
    const int c0 = pr0 ? g_idx_f[b * LL + j0] : 0;
    const int c1 = pr1 ? g_idx_f[b * LL + j1] : 0;

    if (tid < 128) { s_rmax[tid] = NINF; s_cmax[tid] = NINF; }

    const uint32_t* Ptile = g_projb + ((size_t)b * 4 + blockIdx.y) * 16 * 2048 + tid * 8;
    const float* Fb0 = F + ((size_t)b * LL + c0) * DD + gc;
    const float* Fb1 = F + ((size_t)b * LL + c1) * DD + gc;

    uint32_t as_u32[3];
#pragma unroll
    for (int s = 0; s < 3; s++)
        as_u32[s] = (uint32_t)__cvta_generic_to_shared(&As[s][tid * 8]);

    float acc[4][4][4];
#pragma unroll
    for (int i = 0; i < 4; i++)
#pragma unroll
        for (int j = 0; j < 4; j++)
#pragma unroll
            for (int q = 0; q < 4; q++) acc[i][j][q] = 0.0f;

    // prologue
    CP_ASYNC16(as_u32[0],      Ptile);
    CP_ASYNC16(as_u32[0] + 16, Ptile + 4);
    CP_COMMIT();
    CP_ASYNC16(as_u32[1],      Ptile + 2048);
    CP_ASYNC16(as_u32[1] + 16, Ptile + 2048 + 4);
    CP_COMMIT();
    {
        float4 v;
        v = zmask(*(const float4*)(Fb0), pr0);      stB_nm(Bs[0], gr,      0, p0, v);
        v = zmask(*(const float4*)(Fb0 + 16), pr0); stB_nm(Bs[0], gr,      1, p0, v);
        v = zmask(*(const float4*)(Fb1), pr1);      stB_nm(Bs[0], gr + 64, 0, p0, v);
        v = zmask(*(const float4*)(Fb1 + 16), pr1); stB_nm(Bs[0], gr + 64, 1, p0, v);
    }
    CP_WAIT1();
    __syncthreads();

#pragma unroll
    for (int kt = 0; kt < 16; kt++) {
        const int buf2 = kt & 1;
        const int buf3 = kt % 3;
        const bool more = (kt + 1 < 16);

        float4 vb0, vb1, vb2, vb3;
        if (more) {
            const int K0 = (kt + 1) * 32;
            vb0 = zmask(*(const float4*)(Fb0 + K0), pr0);
            vb1 = zmask(*(const float4*)(Fb0 + K0 + 16), pr0);
            vb2 = zmask(*(const float4*)(Fb1 + K0), pr1);
            vb3 = zmask(*(const float4*)(Fb1 + K0 + 16), pr1);
        }
        if (kt + 2 < 16) {
            const int s3 = (kt + 2) % 3;
            CP_ASYNC16(as_u32[s3],      Ptile + (size_t)(kt + 2) * 2048);
            CP_ASYNC16(as_u32[s3] + 16, Ptile + (size_t)(kt + 2) * 2048 + 4);
            CP_COMMIT();
        }

        mma_block(As[buf3], Bs[buf2], 0, wm, wn, physL, acc);
        mma_block(As[buf3], Bs[buf2], 1, wm, wn, physL, acc);

        if (more) {
            stB_nm(Bs[buf2 ^ 1], gr,      0, p0, vb0);
            stB_nm(Bs[buf2 ^ 1], gr,      1, p0, vb1);
            stB_nm(Bs[buf2 ^ 1], gr + 64, 0, p0, vb2);
            stB_nm(Bs[buf2 ^ 1], gr + 64, 1, p0, vb3);
            if (kt + 2 < 16) { CP_WAIT1(); } else { CP_WAIT0(); }
            __syncthreads();
        }
    }

    // fused row/col max epilogue with index scatter
    __syncthreads();
    const int lx = lane & 3, ly = lane >> 2;
#pragma unroll
    for (int mt = 0; mt < 4; mt++) {
#pragma unroll
        for (int h = 0; h < 2; h++) {
            float v = NINF;
#pragma unroll
            for (int nt = 0; nt < 4; nt++)
                v = fmaxf(v, fmaxf(acc[mt][nt][2 * h], acc[mt][nt][2 * h + 1]));
            v = fmaxf(v, __shfl_xor_sync(0xffffffffu, v, 1));
            v = fmaxf(v, __shfl_xor_sync(0xffffffffu, v, 2));
            if (lx == 0) atomicMaxF(&s_rmax[wm * 64 + mt * 16 + ly + h * 8], v);
        }
    }
#pragma unroll
    for (int nt = 0; nt < 4; nt++) {
#pragma unroll
        for (int j = 0; j < 2; j++) {
            float v = NINF;
#pragma unroll
            for (int mt = 0; mt < 4; mt++)
                v = fmaxf(v, fmaxf(acc[mt][nt][j], acc[mt][nt][2 + j]));
            v = fmaxf(v, __shfl_xor_sync(0xffffffffu, v, 4));
            v = fmaxf(v, __shfl_xor_sync(0xffffffffu, v, 8));
            v = fmaxf(v, __shfl_xor_sync(0xffffffffu, v, 16));
            if (lane < 4) atomicMaxF(&s_cmax[wn * 32 + nt * 8 + 2 * lane + j], v);
        }
    }
    __syncthreads();
    if (tid < 128) {
        const int jr = l0 + tid;
        if (jr < cnt_t)
            atomicMaxF(&g_rowmax[b * LL + g_idx_t[b * LL + jr]], s_rmax[tid]);
        const int jc = n0 + tid;
        if (jc < cnt_f)
            atomicMaxF(&g_colmax[b * LL + g_idx_f[b * LL + jc]], s_cmax[tid]);
    }
}

// ----------------------------- softmax ----------------------------------------
__global__ void softmax_kernel() {
    const int idx = blockIdx.x;
    const bool isF = idx >= Bb;
    const int b = isF ? idx - Bb : idx;
    const float* mx = isF ? (g_colmax + b * LL) : (g_rowmax + b * LL);
    const float* mk = isF ? (g_mf + b * LL) : (g_mt + b * LL);
    float* out = isF ? (g_alpha_f + b * LL) : (g_alpha_t + b * LL);
    const int cnt_other = isF ? g_cnt_t[b] : g_cnt_f[b];

    const int tid = threadIdx.x;
    int i0 = tid, i1 = tid + 256;
    float m0v = mk[i0], m1v = mk[i1];
    float x0 = mx[i0], x1 = mx[i1];
    if (cnt_other < 512) { x0 = fmaxf(x0, 0.0f); x1 = fmaxf(x1, 0.0f); }
    float v0 = tanhf(x0) + (m0v - 1.0f) * 1000000.0f;
    float v1 = tanhf(x1) + (m1v - 1.0f) * 1000000.0f;

    __shared__ float red[256];
    red[tid] = fmaxf(v0, v1);
    __syncthreads();
    for (int s = 128; s > 0; s >>= 1) {
        if (tid < s) red[tid] = fmaxf(red[tid], red[tid + s]);
        __syncthreads();
    }
    float vm = red[0];
    __syncthreads();

    float e0 = expf(v0 - vm);
    float e1 = expf(v1 - vm);
    red[tid] = e0 + e1;
    __syncthreads();
    for (int s = 128; s > 0; s >>= 1) {
        if (tid < s) red[tid] += red[tid + s];
        __syncthreads();
    }
    float inv = 1.0f / red[0];
    out[i0] = e0 * inv * m0v;
    out[i1] = e1 * inv * m1v;
}

// ----------------------------- combine (compact) --------------------------------
__global__ void combine_kernel(const float* __restrict__ T,
                               const float* __restrict__ F,
                               float* __restrict__ out)
{
    __shared__ float red[1024];
    const int b = blockIdx.y;
    const int dl = threadIdx.x & 127;
    const int chunk = threadIdx.x >> 7;           // 0..7
    const int d = blockIdx.x * 128 + dl;
    const int* it  = g_idx_t + b * LL;
    const int* ifx = g_idx_f + b * LL;
    const int ct = g_cnt_t[b], cf = g_cnt_f[b];
    const float* at = g_alpha_t + b * LL;
    const float* af = g_alpha_f + b * LL;
    const float* tp = T + (size_t)b * LL * DD + d;
    const float* fp = F + (size_t)b * LL * DD + d;
    const int jb = chunk * 64;

    float a0 = 0.f, a1 = 0.f, a2 = 0.f, a3 = 0.f;
    {
        const int je = min(jb + 64, ct);
        int j = jb;
        for (; j + 4 <= je; j += 4) {
            int l0 = it[j], l1 = it[j + 1], l2 = it[j + 2], l3 = it[j + 3];
            a0 = fmaf(at[l0], tp[(size_t)l0 * DD], a0);
            a1 = fmaf(at[l1], tp[(size_t)l1 * DD], a1);
            a2 = fmaf(at[l2], tp[(size_t)l2 * DD], a2);
            a3 = fmaf(at[l3], tp[(size_t)l3 * DD], a3);
        }
        for (; j < je; j++) {
            int l = it[j];
            a0 = fmaf(at[l], tp[(size_t)l * DD], a0);
        }
    }
    {
        const int je = min(jb + 64, cf);
        int j = jb;
        for (; j + 4 <= je; j += 4) {
            int l0 = ifx[j], l1 = ifx[j + 1], l2 = ifx[j + 2], l3 = ifx[j + 3];
            a0 = fmaf(af[l0], fp[(size_t)l0 * DD], a0);
            a1 = fmaf(af[l1], fp[(size_t)l1 * DD], a1);
            a2 = fmaf(af[l2], fp[(size_t)l2 * DD], a2);
            a3 = fmaf(af[l3], fp[(size_t)l3 * DD], a3);
        }
        for (; j < je; j++) {
            int l = ifx[j];
            a0 = fmaf(af[l], fp[(size_t)l * DD], a0);
        }
    }
    red[threadIdx.x] = (a0 + a1) + (a2 + a3);
    __syncthreads();
    if (chunk == 0) {
        float s = 0.f;
#pragma unroll
        for (int i = 0; i < 8; i++) s += red[dl + 128 * i];
        out[b * DD + d] = s;
    }
}

// ----------------------------- launch -------------------------------------------
extern "C" void kernel_launch(void* const* d_in, const int* in_sizes, int n_in,
                              void* d_out, int out_size)
{
    const float* t  = (const float*)d_in[0];
    const float* f  = (const float*)d_in[1];
    const void*  mt = d_in[2];
    const void*  mf = d_in[3];
    const float* w  = (const float*)d_in[4];
    float* out = (float*)d_out;

    detect_kernel<<<1, 32>>>((const unsigned int*)mt);
    compact_kernel<<<2 * Bb, 512>>>(mt, mf);
    pack_w<<<256, 512>>>(w);
    gemm0_kernel<<<dim3(4, 4, Bb), 256>>>(t);
    gemm1_kernel<<<dim3(4, 4, Bb), 256>>>(f);
    softmax_kernel<<<2 * Bb, 256>>>();
    combine_kernel<<<dim3(4, Bb), 1024>>>(t, f, out);
}

// round 14
// speedup vs baseline: 1.3231x; 1.0912x over previous
#include <cuda_runtime.h>
#include <math.h>
#include <stdint.h>

#define Bb 64
#define LL 512
#define DD 512

// ----------------------------- scratch ---------------------------------------
// proj tiles (8KB) in EXACT mma_block A-fragment order, compact-M rows
__device__ uint32_t g_projb[(size_t)Bb * 4 * 16 * 2048];
// W^T tiles (8KB) in EXACT mma_block B-fragment order
__device__ uint32_t g_wtb2[4 * 16 * 2048];
__device__ float g_mt[Bb * LL];
__device__ float g_mf[Bb * LL];
__device__ int   g_idx_t[Bb * LL];
__device__ int   g_idx_f[Bb * LL];
__device__ int   g_cnt_t[Bb];
__device__ int   g_cnt_f[Bb];
__device__ float g_rowmax[Bb * LL];
__device__ float g_colmax[Bb * LL];
__device__ float g_alpha_t[Bb * LL];
__device__ float g_alpha_f[Bb * LL];

// ----------------------------- helpers ---------------------------------------
__device__ __forceinline__ uint32_t bf16x2_pack(float lo, float hi) {
    uint32_t r;
    asm("cvt.rn.bf16x2.f32 %0, %1, %2;" : "=r"(r) : "f"(hi), "f"(lo));
    return r;
}

__device__ __forceinline__ void mma_bf16(float* c, const uint32_t* a, const uint32_t* b) {
    asm volatile(
        "mma.sync.aligned.m16n8k16.row.col.f32.bf16.bf16.f32 "
        "{%0,%1,%2,%3}, {%4,%5,%6,%7}, {%8,%9}, {%0,%1,%2,%3};\n"
        : "+f"(c[0]), "+f"(c[1]), "+f"(c[2]), "+f"(c[3])
        : "r"(a[0]), "r"(a[1]), "r"(a[2]), "r"(a[3]), "r"(b[0]), "r"(b[1]));
}

#define CP_ASYNC16(sm_u32, gptr) \
    asm volatile("cp.async.cg.shared.global [%0], [%1], 16;" \
                 :: "r"(sm_u32), "l"(gptr) : "memory")
#define CP_COMMIT() asm volatile("cp.async.commit_group;" ::: "memory")
#define CP_WAIT1()  asm volatile("cp.async.wait_group 1;" ::: "memory")
#define CP_WAIT0()  asm volatile("cp.async.wait_group 0;" ::: "memory")

__device__ __forceinline__ void atomicMaxF(float* a, float v) {
    if (v >= 0.0f) atomicMax((int*)a, __float_as_int(v));
    else           atomicMin((unsigned int*)a, __float_as_uint(v));
}

__device__ __forceinline__ float load_mask(const void* p, int i, int fmt) {
    if (fmt == 0) return ((const int*)p)[i] ? 1.0f : 0.0f;
    if (fmt == 1) return ((const float*)p)[i];
    return ((const unsigned char*)p)[i] ? 1.0f : 0.0f;
}

// ---- bf16 fragment-layout writers (mapping validated R5-R13) -------------------
__device__ __forceinline__ void stA_nm(uint32_t* dst, int row, int kk, int p0, float4 v) {
    uint32_t w0 = bf16x2_pack(v.x, v.y);
    uint32_t w1 = bf16x2_pack(v.z, v.w);
    const int base = (((row >> 4) * 2 + kk) << 7) + ((row & 15) >> 3);
    const int rl = (row & 7) * 4;
    int lane = rl + (p0 & 3), phys = lane ^ (lane >> 3);
    dst[base + phys * 4 + ((p0 >> 2) << 1)] = w0;
    int p = p0 + 1;
    lane = rl + (p & 3); phys = lane ^ (lane >> 3);
    dst[base + phys * 4 + ((p >> 2) << 1)] = w1;
}

__device__ __forceinline__ void stB_nm(uint32_t* dst, int col, int kk, int p0, float4 v) {
    uint32_t w0 = bf16x2_pack(v.x, v.y);
    uint32_t w1 = bf16x2_pack(v.z, v.w);
    const int base = (((col >> 3) * 2 + kk) << 6);
    const int rl = (col & 7) * 4;
    int lane = rl + (p0 & 3), phys = lane ^ (lane >> 3);
    dst[base + phys * 2 + (p0 >> 2)] = w0;
    int p = p0 + 1;
    lane = rl + (p & 3); phys = lane ^ (lane >> 3);
    dst[base + phys * 2 + (p >> 2)] = w1;
}

__device__ __forceinline__ float4 zmask(float4 v, bool pred) {
    if (!pred) { v.x = 0.f; v.y = 0.f; v.z = 0.f; v.w = 0.f; }
    return v;
}

// ---- shared MMA block (64x32 warp tile, validated R5-R13) -----------------------
__device__ __forceinline__ void mma_block(const uint32_t* Asb, const uint32_t* Bsb,
                                          int kk, int wm, int wn, int physL,
                                          float acc[4][4][4]) {
    uint4 af[4]; uint2 bfv[4];
#pragma unroll
    for (int mt = 0; mt < 4; mt++)
        af[mt] = *(const uint4*)&Asb[(((wm * 4 + mt) * 2 + kk) << 7) + physL * 4];
#pragma unroll
    for (int nt = 0; nt < 4; nt++)
        bfv[nt] = *(const uint2*)&Bsb[(((wn * 4 + nt) * 2 + kk) << 6) + physL * 2];
#pragma unroll
    for (int mt = 0; mt < 4; mt++)
#pragma unroll
        for (int nt = 0; nt < 4; nt++)
            mma_bf16(acc[mt][nt], (const uint32_t*)&af[mt], (const uint32_t*)&bfv[nt]);
}

// ----------------------------- small kernels ----------------------------------
// fused detect + compact: fmt derived locally from mt[0..255] words
__global__ void compact_kernel(const void* mt, const void* mf) {
    __shared__ int s_i32, s_f32;
    __shared__ int wsum[16];
    __shared__ int wbase[16];

    const int x = blockIdx.x;
    const int b = x >> 1;
    const bool isF = x & 1;
    const int tid = threadIdx.x;

    if (tid == 0) { s_i32 = 1; s_f32 = 1; }
    __syncthreads();
    if (tid < 256) {
        unsigned int w = ((const unsigned int*)mt)[tid];
        if (w > 1u) atomicAnd(&s_i32, 0);
        if (w != 0u && w != 0x3F800000u) atomicAnd(&s_f32, 0);
    }
    __syncthreads();
    const int fmt = s_i32 ? 0 : (s_f32 ? 1 : 2);

    const float mv = load_mask(isF ? mf : mt, b * LL + tid, fmt);
    (isF ? g_mf : g_mt)[b * LL + tid] = mv;
    (isF ? g_colmax : g_rowmax)[b * LL + tid] = __int_as_float(0xff800000);

    const bool on = (mv != 0.0f);
    const unsigned bal = __ballot_sync(0xffffffffu, on);
    const int wid = tid >> 5, lane = tid & 31;
    if (lane == 0) wsum[wid] = __popc(bal);
    __syncthreads();
    if (tid == 0) {
        int s = 0;
        for (int i = 0; i < 16; i++) { wbase[i] = s; s += wsum[i]; }
        if (isF) g_cnt_f[b] = s; else g_cnt_t[b] = s;
    }
    __syncthreads();
    if (on) {
        int pos = wbase[wid] + __popc(bal & ((1u << lane) - 1u));
        (isF ? g_idx_f : g_idx_t)[b * LL + pos] = tid;
    }
}

__global__ void pack_w(const float* __restrict__ W) {
    const int p = blockIdx.x;
    const int n = threadIdx.x;
    const int k0 = p * 2;
    float lo = W[(size_t)k0 * DD + n];
    float hi = W[(size_t)(k0 + 1) * DD + n];
    const int nt = n >> 7, col = n & 127;
    const int kt = p >> 4, kk = (p >> 3) & 1, pl = p & 7;
    const int lane_v = (col & 7) * 4 + (pl & 3);
    const int phys = lane_v ^ (lane_v >> 3);
    const int idx = (nt * 16 + kt) * 2048 +
                    (((col >> 3) * 2 + kk) << 6) + phys * 2 + (pl >> 2);
    g_wtb2[idx] = bf16x2_pack(lo, hi);
}

// ----------------------------- GEMM 0: proj = compact(t) @ W^T ------------------
// BK=64 (two 32-k sub-chunks per stage). A via registers (2-stage, interleaved
// half-staging); B (W) via cp.async (3-stage x 16KB). Dynamic smem 80KB.
__global__ void __launch_bounds__(256, 2) gemm0_kernel(const float* __restrict__ T)
{
    extern __shared__ uint32_t dsm[];
    uint32_t* As2 = dsm;              // 2 stages x 4096 words
    uint32_t* Bs3 = dsm + 8192;       // 3 stages x 4096 words

    const int tid  = threadIdx.x;
    const int lane = tid & 31;
    const int wid  = tid >> 5;
    const int wm   = wid & 1;
    const int wn   = wid >> 1;
    const int b  = blockIdx.z;
    const int l0 = blockIdx.y * 128;
    const int nt_tile = blockIdx.x;

    const int cnt = g_cnt_t[b];
    if (l0 >= cnt) return;

    const int gr = tid >> 2;
    const int gc = (tid & 3) * 4;
    const int p0 = gc >> 1;
    const int physL = lane ^ (lane >> 3);

    const int j0 = l0 + gr, j1 = l0 + gr + 64;
    const bool pr0 = (j0 < cnt), pr1 = (j1 < cnt);
    const int r0 = pr0 ? g_idx_t[b * LL + j0] : 0;
    const int r1 = pr1 ? g_idx_t[b * LL + j1] : 0;

    const float* Ab0 = T + ((size_t)b * LL + r0) * DD + gc;
    const float* Ab1 = T + ((size_t)b * LL + r1) * DD + gc;
    const uint32_t* Wtile = g_wtb2 + (size_t)nt_tile * 16 * 2048 + tid * 8;

    const uint32_t shbase = (uint32_t)__cvta_generic_to_shared(dsm);
    const uint32_t shB = shbase + 8192 * 4 + tid * 32;

    float acc[4][4][4];
#pragma unroll
    for (int i = 0; i < 4; i++)
#pragma unroll
        for (int j = 0; j < 4; j++)
#pragma unroll
            for (int q = 0; q < 4; q++) acc[i][j][q] = 0.0f;

    // prologue: B stages 0 (tiles 0,1) and 1 (tiles 2,3); A ktt0 (subs 0,1)
    CP_ASYNC16(shB,                 Wtile);
    CP_ASYNC16(shB + 16,            Wtile + 4);
    CP_ASYNC16(shB + 8192,          Wtile + 2048);
    CP_ASYNC16(shB + 8192 + 16,     Wtile + 2048 + 4);
    CP_COMMIT();
    CP_ASYNC16(shB + 16384,         Wtile + 4096);
    CP_ASYNC16(shB + 16384 + 16,    Wtile + 4096 + 4);
    CP_ASYNC16(shB + 24576,         Wtile + 6144);
    CP_ASYNC16(shB + 24576 + 16,    Wtile + 6144 + 4);
    CP_COMMIT();
    {
        float4 v;
        v = zmask(*(const float4*)(Ab0), pr0);      stA_nm(As2, gr,      0, p0, v);
        v = zmask(*(const float4*)(Ab0 + 16), pr0); stA_nm(As2, gr,      1, p0, v);
        v = zmask(*(const float4*)(Ab1), pr1);      stA_nm(As2, gr + 64, 0, p0, v);
        v = zmask(*(const float4*)(Ab1 + 16), pr1); stA_nm(As2, gr + 64, 1, p0, v);
        v = zmask(*(const float4*)(Ab0 + 32), pr0); stA_nm(As2 + 2048, gr,      0, p0, v);
        v = zmask(*(const float4*)(Ab0 + 48), pr0); stA_nm(As2 + 2048, gr,      1, p0, v);
        v = zmask(*(const float4*)(Ab1 + 32), pr1); stA_nm(As2 + 2048, gr + 64, 0, p0, v);
        v = zmask(*(const float4*)(Ab1 + 48), pr1); stA_nm(As2 + 2048, gr + 64, 1, p0, v);
    }
    CP_WAIT1();
    __syncthreads();

#pragma unroll
    for (int ktt = 0; ktt < 8; ktt++) {
        const int buf2 = ktt & 1;
        const int buf3 = ktt % 3;
        const bool more = (ktt + 1 < 8);
        const uint32_t* Ac = As2 + buf2 * 4096;
        const uint32_t* Bc = Bs3 + buf3 * 4096;
        uint32_t* An = (uint32_t*)(As2 + (buf2 ^ 1) * 4096);
        const int K0 = (ktt + 1) * 64;

        // prefetch A next-ktt sub0
        float4 va0, va1, va2, va3;
        if (more) {
            va0 = zmask(*(const float4*)(Ab0 + K0), pr0);
            va1 = zmask(*(const float4*)(Ab0 + K0 + 16), pr0);
            va2 = zmask(*(const float4*)(Ab1 + K0), pr1);
            va3 = zmask(*(const float4*)(Ab1 + K0 + 16), pr1);
        }
        if (ktt + 2 < 8) {
            const uint32_t sB = shB + ((ktt + 2) % 3) * 16384;
            const uint32_t* src = Wtile + (size_t)(ktt + 2) * 4096;
            CP_ASYNC16(sB,               src);
            CP_ASYNC16(sB + 16,          src + 4);
            CP_ASYNC16(sB + 8192,        src + 2048);
            CP_ASYNC16(sB + 8192 + 16,   src + 2048 + 4);
            CP_COMMIT();
        }

        mma_block(Ac, Bc, 0, wm, wn, physL, acc);
        mma_block(Ac, Bc, 1, wm, wn, physL, acc);

        if (more) {
            stA_nm(An, gr,      0, p0, va0);
            stA_nm(An, gr,      1, p0, va1);
            stA_nm(An, gr + 64, 0, p0, va2);
            stA_nm(An, gr + 64, 1, p0, va3);
            // prefetch A next-ktt sub1 (reuse regs)
            va0 = zmask(*(const float4*)(Ab0 + K0 + 32), pr0);
            va1 = zmask(*(const float4*)(Ab0 + K0 + 48), pr0);
            va2 = zmask(*(const float4*)(Ab1 + K0 + 32), pr1);
            va3 = zmask(*(const float4*)(Ab1 + K0 + 48), pr1);
        }

        mma_block(Ac + 2048, Bc + 2048, 0, wm, wn, physL, acc);
        mma_block(Ac + 2048, Bc + 2048, 1, wm, wn, physL, acc);

        if (more) {
            stA_nm(An + 2048, gr,      0, p0, va0);
            stA_nm(An + 2048, gr,      1, p0, va1);
            stA_nm(An + 2048, gr + 64, 0, p0, va2);
            stA_nm(An + 2048, gr + 64, 1, p0, va3);
            if (ktt + 2 < 8) { CP_WAIT1(); } else { CP_WAIT0(); }
            __syncthreads();
        }
    }

    // epilogue: proj tiles in EXACT mma_block A-fragment layout (validated R9+)
    const int lx = lane & 3, ly = lane >> 2;
    uint32_t* Ptile = g_projb + ((size_t)b * 4 + blockIdx.y) * 16 * 2048;
#pragma unroll
    for (int mt = 0; mt < 4; mt++) {
        const int mtile = wm * 4 + mt;
#pragma unroll
        for (int nt = 0; nt < 4; nt++) {
            const int c = nt_tile * 128 + wn * 32 + nt * 8 + 2 * lx;
            const int kp_g = c >> 1;
            const int kt1 = kp_g >> 4;
            const int kk1 = (kp_g >> 3) & 1;
            const int kp  = kp_g & 7;
            const int lane_v = ly * 4 + (kp & 3);
            const int phys = lane_v ^ (lane_v >> 3);
            const int si = (kp >= 4) ? 2 : 0;
            const int idx = kt1 * 2048 + (((mtile * 2 + kk1) << 7)) + phys * 4 + si;
            uint2 w;
            w.x = bf16x2_pack(acc[mt][nt][0], acc[mt][nt][1]);
            w.y = bf16x2_pack(acc[mt][nt][2], acc[mt][nt][3]);
            *(uint2*)&Ptile[idx] = w;
        }
    }
}

// ------------- GEMM 1: M = proj(compact) @ compact(f)^T, fused max --------------
// BK=64. A (proj) via cp.async (3-stage x 16KB); B (f) via registers (2-stage).
__global__ void __launch_bounds__(256, 2) gemm1_kernel(const float* __restrict__ F)
{
    extern __shared__ uint32_t dsm[];
    uint32_t* As3 = dsm;              // 3 stages x 4096 words
    uint32_t* Bs2 = dsm + 12288;      // 2 stages x 4096 words
    __shared__ float s_rmax[128];
    __shared__ float s_cmax[128];

    const int tid  = threadIdx.x;
    const int lane = tid & 31;
    const int wid  = tid >> 5;
    const int wm   = wid & 1;
    const int wn   = wid >> 1;
    const int b  = blockIdx.z;
    const int l0 = blockIdx.y * 128;
    const int n0 = blockIdx.x * 128;

    const int cnt_t = g_cnt_t[b];
    const int cnt_f = g_cnt_f[b];
    if (l0 >= cnt_t || n0 >= cnt_f) return;

    const int gr = tid >> 2;
    const int gc = (tid & 3) * 4;
    const int p0 = gc >> 1;
    const int physL = lane ^ (lane >> 3);
    const float NINF = __int_as_float(0xff800000);

    const int j0 = n0 + gr, j1 = n0 + gr + 64;
    const bool pr0 = (j0 < cnt_f), pr1 = (j1 < cnt_f);
    const int c0 = pr0 ? g_idx_f[b * LL + j0] : 0;
    const int c1 = pr1 ? g_idx_f[b * LL + j1] : 0;

    if (tid < 128) { s_rmax[tid] = NINF; s_cmax[tid] = NINF; }

    const uint32_t* Ptile = g_projb + ((size_t)b * 4 + blockIdx.y) * 16 * 2048 + tid * 8;
    const float* Fb0 = F + ((size_t)b * LL + c0) * DD + gc;
    const float* Fb1 = F + ((size_t)b * LL + c1) * DD + gc;

    const uint32_t shbase = (uint32_t)__cvta_generic_to_shared(dsm);
    const uint32_t shA = shbase + tid * 32;

    float acc[4][4][4];
#pragma unroll
    for (int i = 0; i < 4; i++)
#pragma unroll
        for (int j = 0; j < 4; j++)
#pragma unroll
            for (int q = 0; q < 4; q++) acc[i][j][q] = 0.0f;

    // prologue: A stages 0,1 (tiles 0-3); B ktt0 subs 0,1
    CP_ASYNC16(shA,               Ptile);
    CP_ASYNC16(shA + 16,          Ptile + 4);
    CP_ASYNC16(shA + 8192,        Ptile + 2048);
    CP_ASYNC16(shA + 8192 + 16,   Ptile + 2048 + 4);
    CP_COMMIT();
    CP_ASYNC16(shA + 16384,       Ptile + 4096);
    CP_ASYNC16(shA + 16384 + 16,  Ptile + 4096 + 4);
    CP_ASYNC16(shA + 24576,       Ptile + 6144);
    CP_ASYNC16(shA + 24576 + 16,  Ptile + 6144 + 4);
    CP_COMMIT();
    {
        float4 v;
        v = zmask(*(const float4*)(Fb0), pr0);      stB_nm(Bs2, gr,      0, p0, v);
        v = zmask(*(const float4*)(Fb0 + 16), pr0); stB_nm(Bs2, gr,      1, p0, v);
        v = zmask(*(const float4*)(Fb1), pr1);      stB_nm(Bs2, gr + 64, 0, p0, v);
        v = zmask(*(const float4*)(Fb1 + 16), pr1); stB_nm(Bs2, gr + 64, 1, p0, v);
        v = zmask(*(const float4*)(Fb0 + 32), pr0); stB_nm(Bs2 + 2048, gr,      0, p0, v);
        v = zmask(*(const float4*)(Fb0 + 48), pr0); stB_nm(Bs2 + 2048, gr,      1, p0, v);
        v = zmask(*(const float4*)(Fb1 + 32), pr1); stB_nm(Bs2 + 2048, gr + 64, 0, p0, v);
        v = zmask(*(const float4*)(Fb1 + 48), pr1); stB_nm(Bs2 + 2048, gr + 64, 1, p0, v);
    }
    CP_WAIT1();
    __syncthreads();

#pragma unroll
    for (int ktt = 0; ktt < 8; ktt++) {
        const int buf2 = ktt & 1;
        const int buf3 = ktt % 3;
        const bool more = (ktt + 1 < 8);
        const uint32_t* Ac = As3 + buf3 * 4096;
        const uint32_t* Bc = Bs2 + buf2 * 4096;
        uint32_t* Bn = (uint32_t*)(Bs2 + (buf2 ^ 1) * 4096);
        const int K0 = (ktt + 1) * 64;

        float4 vb0, vb1, vb2, vb3;
        if (more) {
            vb0 = zmask(*(const float4*)(Fb0 + K0), pr0);
            vb1 = zmask(*(const float4*)(Fb0 + K0 + 16), pr0);
            vb2 = zmask(*(const float4*)(Fb1 + K0), pr1);
            vb3 = zmask(*(const float4*)(Fb1 + K0 + 16), pr1);
        }
        if (ktt + 2 < 8) {
            const uint32_t sA = shA + ((ktt + 2) % 3) * 16384;
            const uint32_t* src = Ptile + (size_t)(ktt + 2) * 4096;
            CP_ASYNC16(sA,               src);
            CP_ASYNC16(sA + 16,          src + 4);
            CP_ASYNC16(sA + 8192,        src + 2048);
            CP_ASYNC16(sA + 8192 + 16,   src + 2048 + 4);
            CP_COMMIT();
        }

        mma_block(Ac, Bc, 0, wm, wn, physL, acc);
        mma_block(Ac, Bc, 1, wm, wn, physL, acc);

        if (more) {
            stB_nm(Bn, gr,      0, p0, vb0);
            stB_nm(Bn, gr,      1, p0, vb1);
            stB_nm(Bn, gr + 64, 0, p0, vb2);
            stB_nm(Bn, gr + 64, 1, p0, vb3);
            vb0 = zmask(*(const float4*)(Fb0 + K0 + 32), pr0);
            vb1 = zmask(*(const float4*)(Fb0 + K0 + 48), pr0);
            vb2 = zmask(*(const float4*)(Fb1 + K0 + 32), pr1);
            vb3 = zmask(*(const float4*)(Fb1 + K0 + 48), pr1);
        }

        mma_block(Ac + 2048, Bc + 2048, 0, wm, wn, physL, acc);
        mma_block(Ac + 2048, Bc + 2048, 1, wm, wn, physL, acc);

        if (more) {
            stB_nm(Bn + 2048, gr,      0, p0, vb0);
            stB_nm(Bn + 2048, gr,      1, p0, vb1);
            stB_nm(Bn + 2048, gr + 64, 0, p0, vb2);
            stB_nm(Bn + 2048, gr + 64, 1, p0, vb3);
            if (ktt + 2 < 8) { CP_WAIT1(); } else { CP_WAIT0(); }
            __syncthreads();
        }
    }

    // fused row/col max epilogue with index scatter
    __syncthreads();
    const int lx = lane & 3, ly = lane >> 2;
#pragma unroll
    for (int mt = 0; mt < 4; mt++) {
#pragma unroll
        for (int h = 0; h < 2; h++) {
            float v = NINF;
#pragma unroll
            for (int nt = 0; nt < 4; nt++)
                v = fmaxf(v, fmaxf(acc[mt][nt][2 * h], acc[mt][nt][2 * h + 1]));
            v = fmaxf(v, __shfl_xor_sync(0xffffffffu, v, 1));
            v = fmaxf(v, __shfl_xor_sync(0xffffffffu, v, 2));
            if (lx == 0) atomicMaxF(&s_rmax[wm * 64 + mt * 16 + ly + h * 8], v);
        }
    }
#pragma unroll
    for (int nt = 0; nt < 4; nt++) {
#pragma unroll
        for (int j = 0; j < 2; j++) {
            float v = NINF;
#pragma unroll
            for (int mt = 0; mt < 4; mt++)
                v = fmaxf(v, fmaxf(acc[mt][nt][j], acc[mt][nt][2 + j]));
            v = fmaxf(v, __shfl_xor_sync(0xffffffffu, v, 4));
            v = fmaxf(v, __shfl_xor_sync(0xffffffffu, v, 8));
            v = fmaxf(v, __shfl_xor_sync(0xffffffffu, v, 16));
            if (lane < 4) atomicMaxF(&s_cmax[wn * 32 + nt * 8 + 2 * lane + j], v);
        }
    }
    __syncthreads();
    if (tid < 128) {
        const int jr = l0 + tid;
        if (jr < cnt_t)
            atomicMaxF(&g_rowmax[b * LL + g_idx_t[b * LL + jr]], s_rmax[tid]);
        const int jc = n0 + tid;
        if (jc < cnt_f)
            atomicMaxF(&g_colmax[b * LL + g_idx_f[b * LL + jc]], s_cmax[tid]);
    }
}

// ----------------------------- softmax ----------------------------------------
__global__ void softmax_kernel() {
    const int idx = blockIdx.x;
    const bool isF = idx >= Bb;
    const int b = isF ? idx - Bb : idx;
    const float* mx = isF ? (g_colmax + b * LL) : (g_rowmax + b * LL);
    const float* mk = isF ? (g_mf + b * LL) : (g_mt + b * LL);
    float* out = isF ? (g_alpha_f + b * LL) : (g_alpha_t + b * LL);
    const int cnt_other = isF ? g_cnt_t[b] : g_cnt_f[b];

    const int tid = threadIdx.x;
    int i0 = tid, i1 = tid + 256;
    float m0v = mk[i0], m1v = mk[i1];
    float x0 = mx[i0], x1 = mx[i1];
    if (cnt_other < 512) { x0 = fmaxf(x0, 0.0f); x1 = fmaxf(x1, 0.0f); }
    float v0 = tanhf(x0) + (m0v - 1.0f) * 1000000.0f;
    float v1 = tanhf(x1) + (m1v - 1.0f) * 1000000.0f;

    __shared__ float red[256];
    red[tid] = fmaxf(v0, v1);
    __syncthreads();
    for (int s = 128; s > 0; s >>= 1) {
        if (tid < s) red[tid] = fmaxf(red[tid], red[tid + s]);
        __syncthreads();
    }
    float vm = red[0];
    __syncthreads();

    float e0 = expf(v0 - vm);
    float e1 = expf(v1 - vm);
    red[tid] = e0 + e1;
    __syncthreads();
    for (int s = 128; s > 0; s >>= 1) {
        if (tid < s) red[tid] += red[tid + s];
        __syncthreads();
    }
    float inv = 1.0f / red[0];
    out[i0] = e0 * inv * m0v;
    out[i1] = e1 * inv * m1v;
}

// ----------------------------- combine (compact) --------------------------------
__global__ void combine_kernel(const float* __restrict__ T,
                               const float* __restrict__ F,
                               float* __restrict__ out)
{
    __shared__ float red[1024];
    const int b = blockIdx.y;
    const int dl = threadIdx.x & 127;
    const int chunk = threadIdx.x >> 7;           // 0..7
    const int d = blockIdx.x * 128 + dl;
    const int* it  = g_idx_t + b * LL;
    const int* ifx = g_idx_f + b * LL;
    const int ct = g_cnt_t[b], cf = g_cnt_f[b];
    const float* at = g_alpha_t + b * LL;
    const float* af = g_alpha_f + b * LL;
    const float* tp = T + (size_t)b * LL * DD + d;
    const float* fp = F + (size_t)b * LL * DD + d;
    const int jb = chunk * 64;

    float a0 = 0.f, a1 = 0.f, a2 = 0.f, a3 = 0.f;
    {
        const int je = min(jb + 64, ct);
        int j = jb;
        for (; j + 4 <= je; j += 4) {
            int l0 = it[j], l1 = it[j + 1], l2 = it[j + 2], l3 = it[j + 3];
            a0 = fmaf(at[l0], tp[(size_t)l0 * DD], a0);
            a1 = fmaf(at[l1], tp[(size_t)l1 * DD], a1);
            a2 = fmaf(at[l2], tp[(size_t)l2 * DD], a2);
            a3 = fmaf(at[l3], tp[(size_t)l3 * DD], a3);
        }
        for (; j < je; j++) {
            int l = it[j];
            a0 = fmaf(at[l], tp[(size_t)l * DD], a0);
        }
    }
    {
        const int je = min(jb + 64, cf);
        int j = jb;
        for (; j + 4 <= je; j += 4) {
            int l0 = ifx[j], l1 = ifx[j + 1], l2 = ifx[j + 2], l3 = ifx[j + 3];
            a0 = fmaf(af[l0], fp[(size_t)l0 * DD], a0);
            a1 = fmaf(af[l1], fp[(size_t)l1 * DD], a1);
            a2 = fmaf(af[l2], fp[(size_t)l2 * DD], a2);
            a3 = fmaf(af[l3], fp[(size_t)l3 * DD], a3);
        }
        for (; j < je; j++) {
            int l = ifx[j];
            a0 = fmaf(af[l], fp[(size_t)l * DD], a0);
        }
    }
    red[threadIdx.x] = (a0 + a1) + (a2 + a3);
    __syncthreads();
    if (chunk == 0) {
        float s = 0.f;
#pragma unroll
        for (int i = 0; i < 8; i++) s += red[dl + 128 * i];
        out[b * DD + d] = s;
    }
}

// ----------------------------- launch -------------------------------------------
extern "C" void kernel_launch(void* const* d_in, const int* in_sizes, int n_in,
                              void* d_out, int out_size)
{
    const float* t  = (const float*)d_in[0];
    const float* f  = (const float*)d_in[1];
    const void*  mt = d_in[2];
    const void*  mf = d_in[3];
    const float* w  = (const float*)d_in[4];
    float* out = (float*)d_out;

    const int GSMEM = 20480 * 4;   // 80 KB dynamic
    cudaFuncSetAttribute(gemm0_kernel, cudaFuncAttributeMaxDynamicSharedMemorySize, GSMEM);
    cudaFuncSetAttribute(gemm1_kernel, cudaFuncAttributeMaxDynamicSharedMemorySize, GSMEM);

    compact_kernel<<<2 * Bb, 512>>>(mt, mf);
    pack_w<<<256, 512>>>(w);
    gemm0_kernel<<<dim3(4, 4, Bb), 256, GSMEM>>>(t);
    gemm1_kernel<<<dim3(4, 4, Bb), 256, GSMEM>>>(f);
    softmax_kernel<<<2 * Bb, 256>>>();
    combine_kernel<<<dim3(4, Bb), 1024>>>(t, f, out);
}

// round 15
// speedup vs baseline: 1.3523x; 1.0220x over previous
#include <cuda_runtime.h>
#include <math.h>
#include <stdint.h>

#define Bb 64
#define LL 512
#define DD 512

// ----------------------------- scratch ---------------------------------------
__device__ uint32_t g_projb[(size_t)Bb * 4 * 16 * 2048];  // proj tiles, A-frag order
__device__ uint32_t g_wtb2[4 * 16 * 2048];                // W^T tiles, B-frag order
__device__ float g_mt[Bb * LL];
__device__ float g_mf[Bb * LL];
__device__ int   g_idx_t[Bb * LL];
__device__ int   g_idx_f[Bb * LL];
__device__ int   g_cnt_t[Bb];
__device__ int   g_cnt_f[Bb];
__device__ float g_rowmax[Bb * LL];
__device__ float g_colmax[Bb * LL];

// ----------------------------- helpers ---------------------------------------
__device__ __forceinline__ uint32_t bf16x2_pack(float lo, float hi) {
    uint32_t r;
    asm("cvt.rn.bf16x2.f32 %0, %1, %2;" : "=r"(r) : "f"(hi), "f"(lo));
    return r;
}

__device__ __forceinline__ void mma_bf16(float* c, const uint32_t* a, const uint32_t* b) {
    asm volatile(
        "mma.sync.aligned.m16n8k16.row.col.f32.bf16.bf16.f32 "
        "{%0,%1,%2,%3}, {%4,%5,%6,%7}, {%8,%9}, {%0,%1,%2,%3};\n"
        : "+f"(c[0]), "+f"(c[1]), "+f"(c[2]), "+f"(c[3])
        : "r"(a[0]), "r"(a[1]), "r"(a[2]), "r"(a[3]), "r"(b[0]), "r"(b[1]));
}

#define CP_ASYNC16(sm_u32, gptr) \
    asm volatile("cp.async.cg.shared.global [%0], [%1], 16;" \
                 :: "r"(sm_u32), "l"(gptr) : "memory")
#define CP_COMMIT() asm volatile("cp.async.commit_group;" ::: "memory")
#define CP_WAIT1()  asm volatile("cp.async.wait_group 1;" ::: "memory")
#define CP_WAIT0()  asm volatile("cp.async.wait_group 0;" ::: "memory")

__device__ __forceinline__ void atomicMaxF(float* a, float v) {
    if (v >= 0.0f) atomicMax((int*)a, __float_as_int(v));
    else           atomicMin((unsigned int*)a, __float_as_uint(v));
}

__device__ __forceinline__ float load_mask(const void* p, int i, int fmt) {
    if (fmt == 0) return ((const int*)p)[i] ? 1.0f : 0.0f;
    if (fmt == 1) return ((const float*)p)[i];
    return ((const unsigned char*)p)[i] ? 1.0f : 0.0f;
}

__device__ __forceinline__ float4 zmask(float4 v, bool pred) {
    if (!pred) { v.x = 0.f; v.y = 0.f; v.z = 0.f; v.w = 0.f; }
    return v;
}

__device__ __forceinline__ uint2 pkv(float4 v) {
    uint2 u;
    u.x = bf16x2_pack(v.x, v.y);
    u.y = bf16x2_pack(v.z, v.w);
    return u;
}

// ---- fragment-layout store of pre-packed words (mapping validated R5-R14) ------
__device__ __forceinline__ void stA_pw(uint32_t* dst, int row, int kk, int p0, uint32_t w0, uint32_t w1) {
    const int base = (((row >> 4) * 2 + kk) << 7) + ((row & 15) >> 3);
    const int rl = (row & 7) * 4;
    int lane = rl + (p0 & 3), phys = lane ^ (lane >> 3);
    dst[base + phys * 4 + ((p0 >> 2) << 1)] = w0;
    int p = p0 + 1;
    lane = rl + (p & 3); phys = lane ^ (lane >> 3);
    dst[base + phys * 4 + ((p >> 2) << 1)] = w1;
}

__device__ __forceinline__ void stB_pw(uint32_t* dst, int col, int kk, int p0, uint32_t w0, uint32_t w1) {
    const int base = (((col >> 3) * 2 + kk) << 6);
    const int rl = (col & 7) * 4;
    int lane = rl + (p0 & 3), phys = lane ^ (lane >> 3);
    dst[base + phys * 2 + (p0 >> 2)] = w0;
    int p = p0 + 1;
    lane = rl + (p & 3); phys = lane ^ (lane >> 3);
    dst[base + phys * 2 + (p >> 2)] = w1;
}

// ---- shared MMA block (64x32 warp tile, validated R5-R14) -----------------------
__device__ __forceinline__ void mma_block(const uint32_t* Asb, const uint32_t* Bsb,
                                          int kk, int wm, int wn, int physL,
                                          float acc[4][4][4]) {
    uint4 af[4]; uint2 bfv[4];
#pragma unroll
    for (int mt = 0; mt < 4; mt++)
        af[mt] = *(const uint4*)&Asb[(((wm * 4 + mt) * 2 + kk) << 7) + physL * 4];
#pragma unroll
    for (int nt = 0; nt < 4; nt++)
        bfv[nt] = *(const uint2*)&Bsb[(((wn * 4 + nt) * 2 + kk) << 6) + physL * 2];
#pragma unroll
    for (int mt = 0; mt < 4; mt++)
#pragma unroll
        for (int nt = 0; nt < 4; nt++)
            mma_bf16(acc[mt][nt], (const uint32_t*)&af[mt], (const uint32_t*)&bfv[nt]);
}

// ----------------------------- prep: compact + pack_w ---------------------------
__global__ void prep_kernel(const void* mt, const void* mf, const float* __restrict__ W) {
    const int bx = blockIdx.x;
    const int tid = threadIdx.x;   // 512

    if (bx < 128) {
        // fused detect + mask expand + compaction
        __shared__ int s_i32, s_f32;
        __shared__ int wsum[16];
        __shared__ int wbase[16];

        const int b = bx >> 1;
        const bool isF = bx & 1;

        if (tid == 0) { s_i32 = 1; s_f32 = 1; }
        __syncthreads();
        if (tid < 256) {
            unsigned int w = ((const unsigned int*)mt)[tid];
            if (w > 1u) atomicAnd(&s_i32, 0);
            if (w != 0u && w != 0x3F800000u) atomicAnd(&s_f32, 0);
        }
        __syncthreads();
        const int fmt = s_i32 ? 0 : (s_f32 ? 1 : 2);

        const float mv = load_mask(isF ? mf : mt, b * LL + tid, fmt);
        (isF ? g_mf : g_mt)[b * LL + tid] = mv;
        (isF ? g_colmax : g_rowmax)[b * LL + tid] = __int_as_float(0xff800000);

        const bool on = (mv != 0.0f);
        const unsigned bal = __ballot_sync(0xffffffffu, on);
        const int wid = tid >> 5, lane = tid & 31;
        if (lane == 0) wsum[wid] = __popc(bal);
        __syncthreads();
        if (tid == 0) {
            int s = 0;
            for (int i = 0; i < 16; i++) { wbase[i] = s; s += wsum[i]; }
            if (isF) g_cnt_f[b] = s; else g_cnt_t[b] = s;
        }
        __syncthreads();
        if (on) {
            int pos = wbase[wid] + __popc(bal & ((1u << lane) - 1u));
            (isF ? g_idx_f : g_idx_t)[b * LL + pos] = tid;
        }
    } else {
        // pack W into B-fragment tiles
        const int p = bx - 128;     // k-pair 0..255
        const int n = tid;
        const int k0 = p * 2;
        float lo = W[(size_t)k0 * DD + n];
        float hi = W[(size_t)(k0 + 1) * DD + n];
        const int nt = n >> 7, col = n & 127;
        const int kt = p >> 4, kk = (p >> 3) & 1, pl = p & 7;
        const int lane_v = (col & 7) * 4 + (pl & 3);
        const int phys = lane_v ^ (lane_v >> 3);
        const int idx = (nt * 16 + kt) * 2048 +
                        (((col >> 3) * 2 + kk) << 6) + phys * 2 + (pl >> 2);
        g_wtb2[idx] = bf16x2_pack(lo, hi);
    }
}

// ----------------------------- GEMM 0: proj = compact(t) @ W^T ------------------
// BK=64, both operands 3-stage: A packed reg-pipeline (LDG 3-ahead), B cp.async.
__global__ void __launch_bounds__(256, 2) gemm0_kernel(const float* __restrict__ T)
{
    extern __shared__ uint32_t dsm[];
    uint32_t* As3 = dsm;              // packed A: 3 stages x 4096 words
    uint32_t* Bs3 = dsm + 12288;      // async  B: 3 stages x 4096 words

    const int tid  = threadIdx.x;
    const int lane = tid & 31;
    const int wid  = tid >> 5;
    const int wm   = wid & 1;
    const int wn   = wid >> 1;
    const int b  = blockIdx.z;
    const int l0 = blockIdx.y * 128;
    const int nt_tile = blockIdx.x;

    const int cnt = g_cnt_t[b];
    if (l0 >= cnt) return;

    const int gr = tid >> 2;
    const int gc = (tid & 3) * 4;
    const int p0 = gc >> 1;
    const int physL = lane ^ (lane >> 3);

    const int j0 = l0 + gr, j1 = l0 + gr + 64;
    const bool pr0 = (j0 < cnt), pr1 = (j1 < cnt);
    const int r0 = pr0 ? g_idx_t[b * LL + j0] : 0;
    const int r1 = pr1 ? g_idx_t[b * LL + j1] : 0;

    const float* Ab0 = T + ((size_t)b * LL + r0) * DD + gc;
    const float* Ab1 = T + ((size_t)b * LL + r1) * DD + gc;
    const uint32_t* Wtile = g_wtb2 + (size_t)nt_tile * 16 * 2048 + tid * 8;

    const uint32_t shB = (uint32_t)__cvta_generic_to_shared(dsm) + 12288 * 4 + tid * 32;

    float acc[4][4][4];
#pragma unroll
    for (int i = 0; i < 4; i++)
#pragma unroll
        for (int j = 0; j < 4; j++)
#pragma unroll
            for (int q = 0; q < 4; q++) acc[i][j][q] = 0.0f;

    uint32_t pw[16];

#define LDG_PACK_A(KTT) do {                                                  \
    const int K0_ = (KTT) * 64;                                               \
    uint2 u_;                                                                 \
    u_ = pkv(zmask(*(const float4*)(Ab0 + K0_), pr0));      pw[0]=u_.x;  pw[1]=u_.y;  \
    u_ = pkv(zmask(*(const float4*)(Ab0 + K0_ + 16), pr0)); pw[2]=u_.x;  pw[3]=u_.y;  \
    u_ = pkv(zmask(*(const float4*)(Ab1 + K0_), pr1));      pw[4]=u_.x;  pw[5]=u_.y;  \
    u_ = pkv(zmask(*(const float4*)(Ab1 + K0_ + 16), pr1)); pw[6]=u_.x;  pw[7]=u_.y;  \
    u_ = pkv(zmask(*(const float4*)(Ab0 + K0_ + 32), pr0)); pw[8]=u_.x;  pw[9]=u_.y;  \
    u_ = pkv(zmask(*(const float4*)(Ab0 + K0_ + 48), pr0)); pw[10]=u_.x; pw[11]=u_.y; \
    u_ = pkv(zmask(*(const float4*)(Ab1 + K0_ + 32), pr1)); pw[12]=u_.x; pw[13]=u_.y; \
    u_ = pkv(zmask(*(const float4*)(Ab1 + K0_ + 48), pr1)); pw[14]=u_.x; pw[15]=u_.y; \
} while (0)

#define STS_A(Sg) do {                                          \
    uint32_t* S_ = (Sg);                                        \
    stA_pw(S_, gr,      0, p0, pw[0],  pw[1]);                  \
    stA_pw(S_, gr,      1, p0, pw[2],  pw[3]);                  \
    stA_pw(S_, gr + 64, 0, p0, pw[4],  pw[5]);                  \
    stA_pw(S_, gr + 64, 1, p0, pw[6],  pw[7]);                  \
    stA_pw(S_ + 2048, gr,      0, p0, pw[8],  pw[9]);           \
    stA_pw(S_ + 2048, gr,      1, p0, pw[10], pw[11]);          \
    stA_pw(S_ + 2048, gr + 64, 0, p0, pw[12], pw[13]);          \
    stA_pw(S_ + 2048, gr + 64, 1, p0, pw[14], pw[15]);          \
} while (0)

#define CP_B(STAGE, KTT) do {                                   \
    const uint32_t sB_ = shB + (STAGE) * 16384;                 \
    const uint32_t* src_ = Wtile + (size_t)(KTT) * 4096;        \
    CP_ASYNC16(sB_,             src_);                          \
    CP_ASYNC16(sB_ + 16,        src_ + 4);                      \
    CP_ASYNC16(sB_ + 8192,      src_ + 2048);                   \
    CP_ASYNC16(sB_ + 8192 + 16, src_ + 2048 + 4);               \
    CP_COMMIT();                                                \
} while (0)

    // prologue
    CP_B(0, 0);
    CP_B(1, 1);
    LDG_PACK_A(0); STS_A(As3);
    LDG_PACK_A(1); STS_A(As3 + 4096);
    LDG_PACK_A(2);                     // pw holds ktt2
    CP_WAIT1();
    __syncthreads();

#pragma unroll
    for (int ktt = 0; ktt < 8; ktt++) {
        const uint32_t* Ac = As3 + (ktt % 3) * 4096;
        const uint32_t* Bc = Bs3 + (ktt % 3) * 4096;

        if (ktt + 2 < 8) STS_A((uint32_t*)(As3 + ((ktt + 2) % 3) * 4096));
        if (ktt + 3 < 8) LDG_PACK_A(ktt + 3);
        if (ktt + 2 < 8) CP_B((ktt + 2) % 3, ktt + 2);

        mma_block(Ac, Bc, 0, wm, wn, physL, acc);
        mma_block(Ac, Bc, 1, wm, wn, physL, acc);
        mma_block(Ac + 2048, Bc + 2048, 0, wm, wn, physL, acc);
        mma_block(Ac + 2048, Bc + 2048, 1, wm, wn, physL, acc);

        if (ktt + 1 < 8) {
            if (ktt + 2 < 8) { CP_WAIT1(); } else { CP_WAIT0(); }
            __syncthreads();
        }
    }
#undef LDG_PACK_A
#undef STS_A
#undef CP_B

    // epilogue: proj tiles in EXACT mma_block A-fragment layout (validated R9+)
    const int lx = lane & 3, ly = lane >> 2;
    uint32_t* Ptile = g_projb + ((size_t)b * 4 + blockIdx.y) * 16 * 2048;
#pragma unroll
    for (int mt = 0; mt < 4; mt++) {
        const int mtile = wm * 4 + mt;
#pragma unroll
        for (int nt = 0; nt < 4; nt++) {
            const int c = nt_tile * 128 + wn * 32 + nt * 8 + 2 * lx;
            const int kp_g = c >> 1;
            const int kt1 = kp_g >> 4;
            const int kk1 = (kp_g >> 3) & 1;
            const int kp  = kp_g & 7;
            const int lane_v = ly * 4 + (kp & 3);
            const int phys = lane_v ^ (lane_v >> 3);
            const int si = (kp >= 4) ? 2 : 0;
            const int idx = kt1 * 2048 + (((mtile * 2 + kk1) << 7)) + phys * 4 + si;
            uint2 w;
            w.x = bf16x2_pack(acc[mt][nt][0], acc[mt][nt][1]);
            w.y = bf16x2_pack(acc[mt][nt][2], acc[mt][nt][3]);
            *(uint2*)&Ptile[idx] = w;
        }
    }
}

// ------------- GEMM 1: M = proj(compact) @ compact(f)^T, fused max --------------
// BK=64, both operands 3-stage: A cp.async (proj), B packed reg-pipeline (f).
__global__ void __launch_bounds__(256, 2) gemm1_kernel(const float* __restrict__ F)
{
    extern __shared__ uint32_t dsm[];
    uint32_t* As3 = dsm;              // async  A: 3 stages x 4096 words
    uint32_t* Bs3 = dsm + 12288;      // packed B: 3 stages x 4096 words
    __shared__ float s_rmax[128];
    __shared__ float s_cmax[128];

    const int tid  = threadIdx.x;
    const int lane = tid & 31;
    const int wid  = tid >> 5;
    const int wm   = wid & 1;
    const int wn   = wid >> 1;
    const int b  = blockIdx.z;
    const int l0 = blockIdx.y * 128;
    const int n0 = blockIdx.x * 128;

    const int cnt_t = g_cnt_t[b];
    const int cnt_f = g_cnt_f[b];
    if (l0 >= cnt_t || n0 >= cnt_f) return;

    const int gr = tid >> 2;
    const int gc = (tid & 3) * 4;
    const int p0 = gc >> 1;
    const int physL = lane ^ (lane >> 3);
    const float NINF = __int_as_float(0xff800000);

    const int j0 = n0 + gr, j1 = n0 + gr + 64;
    const bool pr0 = (j0 < cnt_f), pr1 = (j1 < cnt_f);
    const int c0 = pr0 ? g_idx_f[b * LL + j0] : 0;
    const int c1 = pr1 ? g_idx_f[b * LL + j1] : 0;

    if (tid < 128) { s_rmax[tid] = NINF; s_cmax[tid] = NINF; }

    const uint32_t* Ptile = g_projb + ((size_t)b * 4 + blockIdx.y) * 16 * 2048 + tid * 8;
    const float* Fb0 = F + ((size_t)b * LL + c0) * DD + gc;
    const float* Fb1 = F + ((size_t)b * LL + c1) * DD + gc;

    const uint32_t shA = (uint32_t)__cvta_generic_to_shared(dsm) + tid * 32;

    float acc[4][4][4];
#pragma unroll
    for (int i = 0; i < 4; i++)
#pragma unroll
        for (int j = 0; j < 4; j++)
#pragma unroll
            for (int q = 0; q < 4; q++) acc[i][j][q] = 0.0f;

    uint32_t pw[16];

#define LDG_PACK_B(KTT) do {                                                  \
    const int K0_ = (KTT) * 64;                                               \
    uint2 u_;                                                                 \
    u_ = pkv(zmask(*(const float4*)(Fb0 + K0_), pr0));      pw[0]=u_.x;  pw[1]=u_.y;  \
    u_ = pkv(zmask(*(const float4*)(Fb0 + K0_ + 16), pr0)); pw[2]=u_.x;  pw[3]=u_.y;  \
    u_ = pkv(zmask(*(const float4*)(Fb1 + K0_), pr1));      pw[4]=u_.x;  pw[5]=u_.y;  \
    u_ = pkv(zmask(*(const float4*)(Fb1 + K0_ + 16), pr1)); pw[6]=u_.x;  pw[7]=u_.y;  \
    u_ = pkv(zmask(*(const float4*)(Fb0 + K0_ + 32), pr0)); pw[8]=u_.x;  pw[9]=u_.y;  \
    u_ = pkv(zmask(*(const float4*)(Fb0 + K0_ + 48), pr0)); pw[10]=u_.x; pw[11]=u_.y; \
    u_ = pkv(zmask(*(const float4*)(Fb1 + K0_ + 32), pr1)); pw[12]=u_.x; pw[13]=u_.y; \
    u_ = pkv(zmask(*(const float4*)(Fb1 + K0_ + 48), pr1)); pw[14]=u_.x; pw[15]=u_.y; \
} while (0)

#define STS_B(Sg) do {                                          \
    uint32_t* S_ = (Sg);                                        \
    stB_pw(S_, gr,      0, p0, pw[0],  pw[1]);                  \
    stB_pw(S_, gr,      1, p0, pw[2],  pw[3]);                  \
    stB_pw(S_, gr + 64, 0, p0, pw[4],  pw[5]);                  \
    stB_pw(S_, gr + 64, 1, p0, pw[6],  pw[7]);                  \
    stB_pw(S_ + 2048, gr,      0, p0, pw[8],  pw[9]);           \
    stB_pw(S_ + 2048, gr,      1, p0, pw[10], pw[11]);          \
    stB_pw(S_ + 2048, gr + 64, 0, p0, pw[12], pw[13]);          \
    stB_pw(S_ + 2048, gr + 64, 1, p0, pw[14], pw[15]);          \
} while (0)

#define CP_A(STAGE, KTT) do {                                   \
    const uint32_t sA_ = shA + (STAGE) * 16384;                 \
    const uint32_t* src_ = Ptile + (size_t)(KTT) * 4096;        \
    CP_ASYNC16(sA_,             src_);                          \
    CP_ASYNC16(sA_ + 16,        src_ + 4);                      \
    CP_ASYNC16(sA_ + 8192,      src_ + 2048);                   \
    CP_ASYNC16(sA_ + 8192 + 16, src_ + 2048 + 4);               \
    CP_COMMIT();                                                \
} while (0)

    // prologue
    CP_A(0, 0);
    CP_A(1, 1);
    LDG_PACK_B(0); STS_B(Bs3);
    LDG_PACK_B(1); STS_B(Bs3 + 4096);
    LDG_PACK_B(2);
    CP_WAIT1();
    __syncthreads();

#pragma unroll
    for (int ktt = 0; ktt < 8; ktt++) {
        const uint32_t* Ac = As3 + (ktt % 3) * 4096;
        const uint32_t* Bc = Bs3 + (ktt % 3) * 4096;

        if (ktt + 2 < 8) STS_B((uint32_t*)(Bs3 + ((ktt + 2) % 3) * 4096));
        if (ktt + 3 < 8) LDG_PACK_B(ktt + 3);
        if (ktt + 2 < 8) CP_A((ktt + 2) % 3, ktt + 2);

        mma_block(Ac, Bc, 0, wm, wn, physL, acc);
        mma_block(Ac, Bc, 1, wm, wn, physL, acc);
        mma_block(Ac + 2048, Bc + 2048, 0, wm, wn, physL, acc);
        mma_block(Ac + 2048, Bc + 2048, 1, wm, wn, physL, acc);

        if (ktt + 1 < 8) {
            if (ktt + 2 < 8) { CP_WAIT1(); } else { CP_WAIT0(); }
            __syncthreads();
        }
    }
#undef LDG_PACK_B
#undef STS_B
#undef CP_A

    // fused row/col max epilogue with index scatter
    __syncthreads();
    const int lx = lane & 3, ly = lane >> 2;
#pragma unroll
    for (int mt = 0; mt < 4; mt++) {
#pragma unroll
        for (int h = 0; h < 2; h++) {
            float v = NINF;
#pragma unroll
            for (int nt = 0; nt < 4; nt++)
                v = fmaxf(v, fmaxf(acc[mt][nt][2 * h], acc[mt][nt][2 * h + 1]));
            v = fmaxf(v, __shfl_xor_sync(0xffffffffu, v, 1));
            v = fmaxf(v, __shfl_xor_sync(0xffffffffu, v, 2));
            if (lx == 0) atomicMaxF(&s_rmax[wm * 64 + mt * 16 + ly + h * 8], v);
        }
    }
#pragma unroll
    for (int nt = 0; nt < 4; nt++) {
#pragma unroll
        for (int j = 0; j < 2; j++) {
            float v = NINF;
#pragma unroll
            for (int mt = 0; mt < 4; mt++)
                v = fmaxf(v, fmaxf(acc[mt][nt][j], acc[mt][nt][2 + j]));
            v = fmaxf(v, __shfl_xor_sync(0xffffffffu, v, 4));
            v = fmaxf(v, __shfl_xor_sync(0xffffffffu, v, 8));
            v = fmaxf(v, __shfl_xor_sync(0xffffffffu, v, 16));
            if (lane < 4) atomicMaxF(&s_cmax[wn * 32 + nt * 8 + 2 * lane + j], v);
        }
    }
    __syncthreads();
    if (tid < 128) {
        const int jr = l0 + tid;
        if (jr < cnt_t)
            atomicMaxF(&g_rowmax[b * LL + g_idx_t[b * LL + jr]], s_rmax[tid]);
        const int jc = n0 + tid;
        if (jc < cnt_f)
            atomicMaxF(&g_colmax[b * LL + g_idx_f[b * LL + jc]], s_cmax[tid]);
    }
}

// ----------------------------- combine (softmax fused) --------------------------
// grid (4, Bb), block 1024. Each block recomputes its batch's two softmaxes in
// smem (trivial), then does the compact gathers reading alpha from smem.
__global__ void combine_kernel(const float* __restrict__ T,
                               const float* __restrict__ F,
                               float* __restrict__ out)
{
    __shared__ float s_alpha[1024];   // [0:512) alpha_t, [512:1024) alpha_f
    __shared__ float s_red[1024];
    const int b = blockIdx.y;
    const int tid = threadIdx.x;

    // --- softmax phase ---
    {
        const bool isF = tid >= 512;
        const int i = tid & 511;
        const float* mx = isF ? (g_colmax + b * LL) : (g_rowmax + b * LL);
        const float* mk = isF ? (g_mf + b * LL) : (g_mt + b * LL);
        const int cnt_other = isF ? g_cnt_t[b] : g_cnt_f[b];

        float mv = mk[i];
        float x = mx[i];
        if (cnt_other < 512) x = fmaxf(x, 0.0f);
        float v = tanhf(x) + (mv - 1.0f) * 1000000.0f;

        s_red[tid] = v;
        __syncthreads();
        for (int s = 256; s > 0; s >>= 1) {
            if ((tid & 511) < s) s_red[tid] = fmaxf(s_red[tid], s_red[tid + s]);
            __syncthreads();
        }
        float vm = s_red[tid & 512];
        __syncthreads();
        float e = expf(v - vm);
        s_red[tid] = e;
        __syncthreads();
        for (int s = 256; s > 0; s >>= 1) {
            if ((tid & 511) < s) s_red[tid] += s_red[tid + s];
            __syncthreads();
        }
        float inv = 1.0f / s_red[tid & 512];
        s_alpha[tid] = e * inv * mv;
    }
    __syncthreads();

    // --- combine phase ---
    const int dl = tid & 127;
    const int chunk = tid >> 7;           // 0..7
    const int d = blockIdx.x * 128 + dl;
    const int* it  = g_idx_t + b * LL;
    const int* ifx = g_idx_f + b * LL;
    const int ct = g_cnt_t[b], cf = g_cnt_f[b];
    const float* tp = T + (size_t)b * LL * DD + d;
    const float* fp = F + (size_t)b * LL * DD + d;
    const int jb = chunk * 64;

    float a0 = 0.f, a1 = 0.f, a2 = 0.f, a3 = 0.f;
    {
        const int je = min(jb + 64, ct);
        int j = jb;
        for (; j + 4 <= je; j += 4) {
            int l0 = it[j], l1 = it[j + 1], l2 = it[j + 2], l3 = it[j + 3];
            a0 = fmaf(s_alpha[l0], tp[(size_t)l0 * DD], a0);
            a1 = fmaf(s_alpha[l1], tp[(size_t)l1 * DD], a1);
            a2 = fmaf(s_alpha[l2], tp[(size_t)l2 * DD], a2);
            a3 = fmaf(s_alpha[l3], tp[(size_t)l3 * DD], a3);
        }
        for (; j < je; j++) {
            int l = it[j];
            a0 = fmaf(s_alpha[l], tp[(size_t)l * DD], a0);
        }
    }
    {
        const int je = min(jb + 64, cf);
        int j = jb;
        for (; j + 4 <= je; j += 4) {
            int l0 = ifx[j], l1 = ifx[j + 1], l2 = ifx[j + 2], l3 = ifx[j + 3];
            a0 = fmaf(s_alpha[512 + l0], fp[(size_t)l0 * DD], a0);
            a1 = fmaf(s_alpha[512 + l1], fp[(size_t)l1 * DD], a1);
            a2 = fmaf(s_alpha[512 + l2], fp[(size_t)l2 * DD], a2);
            a3 = fmaf(s_alpha[512 + l3], fp[(size_t)l3 * DD], a3);
        }
        for (; j < je; j++) {
            int l = ifx[j];
            a0 = fmaf(s_alpha[512 + l], fp[(size_t)l * DD], a0);
        }
    }
    s_red[tid] = (a0 + a1) + (a2 + a3);
    __syncthreads();
    if (chunk == 0) {
        float s = 0.f;
#pragma unroll
        for (int i = 0; i < 8; i++) s += s_red[dl + 128 * i];
        out[b * DD + d] = s;
    }
}

// ----------------------------- launch -------------------------------------------
extern "C" void kernel_launch(void* const* d_in, const int* in_sizes, int n_in,
                              void* d_out, int out_size)
{
    const float* t  = (const float*)d_in[0];
    const float* f  = (const float*)d_in[1];
    const void*  mt = d_in[2];
    const void*  mf = d_in[3];
    const float* w  = (const float*)d_in[4];
    float* out = (float*)d_out;

    const int GSMEM = 24576 * 4;   // 96 KB dynamic
    cudaFuncSetAttribute(gemm0_kernel, cudaFuncAttributeMaxDynamicSharedMemorySize, GSMEM);
    cudaFuncSetAttribute(gemm1_kernel, cudaFuncAttributeMaxDynamicSharedMemorySize, GSMEM);

    prep_kernel<<<128 + 256, 512>>>(mt, mf, w);
    gemm0_kernel<<<dim3(4, 4, Bb), 256, GSMEM>>>(t);
    gemm1_kernel<<<dim3(4, 4, Bb), 256, GSMEM>>>(f);
    combine_kernel<<<dim3(4, Bb), 1024>>>(t, f, out);
}

// round 16
// speedup vs baseline: 1.3951x; 1.0317x over previous
#include <cuda_runtime.h>
#include <math.h>
#include <stdint.h>

#define Bb 64
#define LL 512
#define DD 512

// ----------------------------- scratch ---------------------------------------
__device__ uint32_t g_projb[(size_t)Bb * 4 * 16 * 2048];  // proj tiles, A-frag order
__device__ uint32_t g_wtb2[4 * 16 * 2048];                // W^T tiles, B-frag order
__device__ float g_mt[Bb * LL];
__device__ float g_mf[Bb * LL];
__device__ int   g_idx_t[Bb * LL];
__device__ int   g_idx_f[Bb * LL];
__device__ int   g_cnt_t[Bb];
__device__ int   g_cnt_f[Bb];
__device__ float g_rowmax[Bb * LL];
__device__ float g_colmax[Bb * LL];

// ----------------------------- helpers ---------------------------------------
__device__ __forceinline__ uint32_t bf16x2_pack(float lo, float hi) {
    uint32_t r;
    asm("cvt.rn.bf16x2.f32 %0, %1, %2;" : "=r"(r) : "f"(hi), "f"(lo));
    return r;
}

__device__ __forceinline__ void mma_bf16(float* c, const uint32_t* a, const uint32_t* b) {
    asm volatile(
        "mma.sync.aligned.m16n8k16.row.col.f32.bf16.bf16.f32 "
        "{%0,%1,%2,%3}, {%4,%5,%6,%7}, {%8,%9}, {%0,%1,%2,%3};\n"
        : "+f"(c[0]), "+f"(c[1]), "+f"(c[2]), "+f"(c[3])
        : "r"(a[0]), "r"(a[1]), "r"(a[2]), "r"(a[3]), "r"(b[0]), "r"(b[1]));
}

#define CP_ASYNC16(sm_u32, gptr) \
    asm volatile("cp.async.cg.shared.global [%0], [%1], 16;" \
                 :: "r"(sm_u32), "l"(gptr) : "memory")
#define CP_COMMIT() asm volatile("cp.async.commit_group;" ::: "memory")
#define CP_WAIT1()  asm volatile("cp.async.wait_group 1;" ::: "memory")
#define CP_WAIT0()  asm volatile("cp.async.wait_group 0;" ::: "memory")

__device__ __forceinline__ void atomicMaxF(float* a, float v) {
    if (v >= 0.0f) atomicMax((int*)a, __float_as_int(v));
    else           atomicMin((unsigned int*)a, __float_as_uint(v));
}

__device__ __forceinline__ float load_mask(const void* p, int i, int fmt) {
    if (fmt == 0) return ((const int*)p)[i] ? 1.0f : 0.0f;
    if (fmt == 1) return ((const float*)p)[i];
    return ((const unsigned char*)p)[i] ? 1.0f : 0.0f;
}

__device__ __forceinline__ float4 zmask(float4 v, bool pred) {
    if (!pred) { v.x = 0.f; v.y = 0.f; v.z = 0.f; v.w = 0.f; }
    return v;
}

__device__ __forceinline__ uint2 pkv(float4 v) {
    uint2 u;
    u.x = bf16x2_pack(v.x, v.y);
    u.y = bf16x2_pack(v.z, v.w);
    return u;
}

// ---- fragment-layout store of pre-packed words (mapping validated R5-R15) ------
__device__ __forceinline__ void stA_pw(uint32_t* dst, int row, int kk, int p0, uint32_t w0, uint32_t w1) {
    const int base = (((row >> 4) * 2 + kk) << 7) + ((row & 15) >> 3);
    const int rl = (row & 7) * 4;
    int lane = rl + (p0 & 3), phys = lane ^ (lane >> 3);
    dst[base + phys * 4 + ((p0 >> 2) << 1)] = w0;
    int p = p0 + 1;
    lane = rl + (p & 3); phys = lane ^ (lane >> 3);
    dst[base + phys * 4 + ((p >> 2) << 1)] = w1;
}

__device__ __forceinline__ void stB_pw(uint32_t* dst, int col, int kk, int p0, uint32_t w0, uint32_t w1) {
    const int base = (((col >> 3) * 2 + kk) << 6);
    const int rl = (col & 7) * 4;
    int lane = rl + (p0 & 3), phys = lane ^ (lane >> 3);
    dst[base + phys * 2 + (p0 >> 2)] = w0;
    int p = p0 + 1;
    lane = rl + (p & 3); phys = lane ^ (lane >> 3);
    dst[base + phys * 2 + (p >> 2)] = w1;
}

// ---- shared MMA block (64x32 warp tile, validated R5-R15) -----------------------
__device__ __forceinline__ void mma_block(const uint32_t* Asb, const uint32_t* Bsb,
                                          int kk, int wm, int wn, int physL,
                                          float acc[4][4][4]) {
    uint4 af[4]; uint2 bfv[4];
#pragma unroll
    for (int mt = 0; mt < 4; mt++)
        af[mt] = *(const uint4*)&Asb[(((wm * 4 + mt) * 2 + kk) << 7) + physL * 4];
#pragma unroll
    for (int nt = 0; nt < 4; nt++)
        bfv[nt] = *(const uint2*)&Bsb[(((wn * 4 + nt) * 2 + kk) << 6) + physL * 2];
#pragma unroll
    for (int mt = 0; mt < 4; mt++)
#pragma unroll
        for (int nt = 0; nt < 4; nt++)
            mma_bf16(acc[mt][nt], (const uint32_t*)&af[mt], (const uint32_t*)&bfv[nt]);
}

// ----------------------------- prep: compact + pack_w ---------------------------
__global__ void prep_kernel(const void* mt, const void* mf, const float* __restrict__ W) {
    const int bx = blockIdx.x;
    const int tid = threadIdx.x;   // 512

    if (bx < 128) {
        __shared__ int s_i32, s_f32;
        __shared__ int wsum[16];
        __shared__ int wbase[16];

        const int b = bx >> 1;
        const bool isF = bx & 1;

        if (tid == 0) { s_i32 = 1; s_f32 = 1; }
        __syncthreads();
        if (tid < 256) {
            unsigned int w = ((const unsigned int*)mt)[tid];
            if (w > 1u) atomicAnd(&s_i32, 0);
            if (w != 0u && w != 0x3F800000u) atomicAnd(&s_f32, 0);
        }
        __syncthreads();
        const int fmt = s_i32 ? 0 : (s_f32 ? 1 : 2);

        const float mv = load_mask(isF ? mf : mt, b * LL + tid, fmt);
        (isF ? g_mf : g_mt)[b * LL + tid] = mv;
        (isF ? g_colmax : g_rowmax)[b * LL + tid] = __int_as_float(0xff800000);

        const bool on = (mv != 0.0f);
        const unsigned bal = __ballot_sync(0xffffffffu, on);
        const int wid = tid >> 5, lane = tid & 31;
        if (lane == 0) wsum[wid] = __popc(bal);
        __syncthreads();
        if (tid == 0) {
            int s = 0;
            for (int i = 0; i < 16; i++) { wbase[i] = s; s += wsum[i]; }
            if (isF) g_cnt_f[b] = s; else g_cnt_t[b] = s;
        }
        __syncthreads();
        if (on) {
            int pos = wbase[wid] + __popc(bal & ((1u << lane) - 1u));
            (isF ? g_idx_f : g_idx_t)[b * LL + pos] = tid;
        }
    } else {
        const int p = bx - 128;     // k-pair 0..255
        const int n = tid;
        const int k0 = p * 2;
        float lo = W[(size_t)k0 * DD + n];
        float hi = W[(size_t)(k0 + 1) * DD + n];
        const int nt = n >> 7, col = n & 127;
        const int kt = p >> 4, kk = (p >> 3) & 1, pl = p & 7;
        const int lane_v = (col & 7) * 4 + (pl & 3);
        const int phys = lane_v ^ (lane_v >> 3);
        const int idx = (nt * 16 + kt) * 2048 +
                        (((col >> 3) * 2 + kk) << 6) + phys * 2 + (pl >> 2);
        g_wtb2[idx] = bf16x2_pack(lo, hi);
    }
}

// ----------------------------- GEMM 0: proj = compact(t) @ W^T ------------------
__global__ void __launch_bounds__(256, 2) gemm0_kernel(const float* __restrict__ T)
{
    extern __shared__ uint32_t dsm[];
    uint32_t* As3 = dsm;              // packed A: 3 stages x 4096 words
    uint32_t* Bs3 = dsm + 12288;      // async  B: 3 stages x 4096 words

    const int tid  = threadIdx.x;
    const int lane = tid & 31;
    const int wid  = tid >> 5;
    const int wm   = wid & 1;
    const int wn   = wid >> 1;
    const int b  = blockIdx.z;
    const int l0 = blockIdx.y * 128;
    const int nt_tile = blockIdx.x;

    const int cnt = g_cnt_t[b];
    if (l0 >= cnt) return;

    const int gr = tid >> 2;
    const int gc = (tid & 3) * 4;
    const int p0 = gc >> 1;
    const int physL = lane ^ (lane >> 3);

    const int j0 = l0 + gr, j1 = l0 + gr + 64;
    const bool pr0 = (j0 < cnt), pr1 = (j1 < cnt);
    const int r0 = pr0 ? g_idx_t[b * LL + j0] : 0;
    const int r1 = pr1 ? g_idx_t[b * LL + j1] : 0;

    const float* Ab0 = T + ((size_t)b * LL + r0) * DD + gc;
    const float* Ab1 = T + ((size_t)b * LL + r1) * DD + gc;
    const uint32_t* Wtile = g_wtb2 + (size_t)nt_tile * 16 * 2048 + tid * 8;

    const uint32_t shB = (uint32_t)__cvta_generic_to_shared(dsm) + 12288 * 4 + tid * 32;

    float acc[4][4][4];
#pragma unroll
    for (int i = 0; i < 4; i++)
#pragma unroll
        for (int j = 0; j < 4; j++)
#pragma unroll
            for (int q = 0; q < 4; q++) acc[i][j][q] = 0.0f;

    uint32_t pw[16];

#define LDG_PACK_A(KTT) do {                                                  \
    const int K0_ = (KTT) * 64;                                               \
    uint2 u_;                                                                 \
    u_ = pkv(zmask(*(const float4*)(Ab0 + K0_), pr0));      pw[0]=u_.x;  pw[1]=u_.y;  \
    u_ = pkv(zmask(*(const float4*)(Ab0 + K0_ + 16), pr0)); pw[2]=u_.x;  pw[3]=u_.y;  \
    u_ = pkv(zmask(*(const float4*)(Ab1 + K0_), pr1));      pw[4]=u_.x;  pw[5]=u_.y;  \
    u_ = pkv(zmask(*(const float4*)(Ab1 + K0_ + 16), pr1)); pw[6]=u_.x;  pw[7]=u_.y;  \
    u_ = pkv(zmask(*(const float4*)(Ab0 + K0_ + 32), pr0)); pw[8]=u_.x;  pw[9]=u_.y;  \
    u_ = pkv(zmask(*(const float4*)(Ab0 + K0_ + 48), pr0)); pw[10]=u_.x; pw[11]=u_.y; \
    u_ = pkv(zmask(*(const float4*)(Ab1 + K0_ + 32), pr1)); pw[12]=u_.x; pw[13]=u_.y; \
    u_ = pkv(zmask(*(const float4*)(Ab1 + K0_ + 48), pr1)); pw[14]=u_.x; pw[15]=u_.y; \
} while (0)

#define STS_A(Sg) do {                                          \
    uint32_t* S_ = (Sg);                                        \
    stA_pw(S_, gr,      0, p0, pw[0],  pw[1]);                  \
    stA_pw(S_, gr,      1, p0, pw[2],  pw[3]);                  \
    stA_pw(S_, gr + 64, 0, p0, pw[4],  pw[5]);                  \
    stA_pw(S_, gr + 64, 1, p0, pw[6],  pw[7]);                  \
    stA_pw(S_ + 2048, gr,      0, p0, pw[8],  pw[9]);           \
    stA_pw(S_ + 2048, gr,      1, p0, pw[10], pw[11]);          \
    stA_pw(S_ + 2048, gr + 64, 0, p0, pw[12], pw[13]);          \
    stA_pw(S_ + 2048, gr + 64, 1, p0, pw[14], pw[15]);          \
} while (0)

#define CP_B(STAGE, KTT) do {                                   \
    const uint32_t sB_ = shB + (STAGE) * 16384;                 \
    const uint32_t* src_ = Wtile + (size_t)(KTT) * 4096;        \
    CP_ASYNC16(sB_,             src_);                          \
    CP_ASYNC16(sB_ + 16,        src_ + 4);                      \
    CP_ASYNC16(sB_ + 8192,      src_ + 2048);                   \
    CP_ASYNC16(sB_ + 8192 + 16, src_ + 2048 + 4);               \
    CP_COMMIT();                                                \
} while (0)

    // prologue
    CP_B(0, 0);
    CP_B(1, 1);
    LDG_PACK_A(0); STS_A(As3);
    LDG_PACK_A(1); STS_A(As3 + 4096);
    LDG_PACK_A(2);
    CP_WAIT1();
    __syncthreads();

#pragma unroll
    for (int ktt = 0; ktt < 8; ktt++) {
        const uint32_t* Ac = As3 + (ktt % 3) * 4096;
        const uint32_t* Bc = Bs3 + (ktt % 3) * 4096;

        if (ktt + 2 < 8) STS_A((uint32_t*)(As3 + ((ktt + 2) % 3) * 4096));
        if (ktt + 3 < 8) LDG_PACK_A(ktt + 3);
        if (ktt + 2 < 8) CP_B((ktt + 2) % 3, ktt + 2);

        mma_block(Ac, Bc, 0, wm, wn, physL, acc);
        mma_block(Ac, Bc, 1, wm, wn, physL, acc);
        mma_block(Ac + 2048, Bc + 2048, 0, wm, wn, physL, acc);
        mma_block(Ac + 2048, Bc + 2048, 1, wm, wn, physL, acc);

        if (ktt + 1 < 8) {
            if (ktt + 2 < 8) { CP_WAIT1(); } else { CP_WAIT0(); }
            __syncthreads();
        }
    }
#undef LDG_PACK_A
#undef STS_A
#undef CP_B

    // epilogue: proj tiles in EXACT mma_block A-fragment layout
    const int lx = lane & 3, ly = lane >> 2;
    uint32_t* Ptile = g_projb + ((size_t)b * 4 + blockIdx.y) * 16 * 2048;
#pragma unroll
    for (int mt = 0; mt < 4; mt++) {
        const int mtile = wm * 4 + mt;
#pragma unroll
        for (int nt = 0; nt < 4; nt++) {
            const int c = nt_tile * 128 + wn * 32 + nt * 8 + 2 * lx;
            const int kp_g = c >> 1;
            const int kt1 = kp_g >> 4;
            const int kk1 = (kp_g >> 3) & 1;
            const int kp  = kp_g & 7;
            const int lane_v = ly * 4 + (kp & 3);
            const int phys = lane_v ^ (lane_v >> 3);
            const int si = (kp >= 4) ? 2 : 0;
            const int idx = kt1 * 2048 + (((mtile * 2 + kk1) << 7)) + phys * 4 + si;
            uint2 w;
            w.x = bf16x2_pack(acc[mt][nt][0], acc[mt][nt][1]);
            w.y = bf16x2_pack(acc[mt][nt][2], acc[mt][nt][3]);
            *(uint2*)&Ptile[idx] = w;
        }
    }
}

// ------------- GEMM 1: M = proj(compact) @ compact(f)^T, fused max --------------
__global__ void __launch_bounds__(256, 2) gemm1_kernel(const float* __restrict__ F)
{
    extern __shared__ uint32_t dsm[];
    uint32_t* As3 = dsm;              // async  A: 3 stages x 4096 words
    uint32_t* Bs3 = dsm + 12288;      // packed B: 3 stages x 4096 words
    __shared__ float s_rmax[128];
    __shared__ float s_cmax[128];

    const int tid  = threadIdx.x;
    const int lane = tid & 31;
    const int wid  = tid >> 5;
    const int wm   = wid & 1;
    const int wn   = wid >> 1;
    const int b  = blockIdx.z;
    const int l0 = blockIdx.y * 128;
    const int n0 = blockIdx.x * 128;

    const int cnt_t = g_cnt_t[b];
    const int cnt_f = g_cnt_f[b];
    if (l0 >= cnt_t || n0 >= cnt_f) return;

    const int gr = tid >> 2;
    const int gc = (tid & 3) * 4;
    const int p0 = gc >> 1;
    const int physL = lane ^ (lane >> 3);
    const float NINF = __int_as_float(0xff800000);

    const int j0 = n0 + gr, j1 = n0 + gr + 64;
    const bool pr0 = (j0 < cnt_f), pr1 = (j1 < cnt_f);
    const int c0 = pr0 ? g_idx_f[b * LL + j0] : 0;
    const int c1 = pr1 ? g_idx_f[b * LL + j1] : 0;

    if (tid < 128) { s_rmax[tid] = NINF; s_cmax[tid] = NINF; }

    const uint32_t* Ptile = g_projb + ((size_t)b * 4 + blockIdx.y) * 16 * 2048 + tid * 8;
    const float* Fb0 = F + ((size_t)b * LL + c0) * DD + gc;
    const float* Fb1 = F + ((size_t)b * LL + c1) * DD + gc;

    const uint32_t shA = (uint32_t)__cvta_generic_to_shared(dsm) + tid * 32;

    float acc[4][4][4];
#pragma unroll
    for (int i = 0; i < 4; i++)
#pragma unroll
        for (int j = 0; j < 4; j++)
#pragma unroll
            for (int q = 0; q < 4; q++) acc[i][j][q] = 0.0f;

    uint32_t pw[16];

#define LDG_PACK_B(KTT) do {                                                  \
    const int K0_ = (KTT) * 64;                                               \
    uint2 u_;                                                                 \
    u_ = pkv(zmask(*(const float4*)(Fb0 + K0_), pr0));      pw[0]=u_.x;  pw[1]=u_.y;  \
    u_ = pkv(zmask(*(const float4*)(Fb0 + K0_ + 16), pr0)); pw[2]=u_.x;  pw[3]=u_.y;  \
    u_ = pkv(zmask(*(const float4*)(Fb1 + K0_), pr1));      pw[4]=u_.x;  pw[5]=u_.y;  \
    u_ = pkv(zmask(*(const float4*)(Fb1 + K0_ + 16), pr1)); pw[6]=u_.x;  pw[7]=u_.y;  \
    u_ = pkv(zmask(*(const float4*)(Fb0 + K0_ + 32), pr0)); pw[8]=u_.x;  pw[9]=u_.y;  \
    u_ = pkv(zmask(*(const float4*)(Fb0 + K0_ + 48), pr0)); pw[10]=u_.x; pw[11]=u_.y; \
    u_ = pkv(zmask(*(const float4*)(Fb1 + K0_ + 32), pr1)); pw[12]=u_.x; pw[13]=u_.y; \
    u_ = pkv(zmask(*(const float4*)(Fb1 + K0_ + 48), pr1)); pw[14]=u_.x; pw[15]=u_.y; \
} while (0)

#define STS_B(Sg) do {                                          \
    uint32_t* S_ = (Sg);                                        \
    stB_pw(S_, gr,      0, p0, pw[0],  pw[1]);                  \
    stB_pw(S_, gr,      1, p0, pw[2],  pw[3]);                  \
    stB_pw(S_, gr + 64, 0, p0, pw[4],  pw[5]);                  \
    stB_pw(S_, gr + 64, 1, p0, pw[6],  pw[7]);                  \
    stB_pw(S_ + 2048, gr,      0, p0, pw[8],  pw[9]);           \
    stB_pw(S_ + 2048, gr,      1, p0, pw[10], pw[11]);          \
    stB_pw(S_ + 2048, gr + 64, 0, p0, pw[12], pw[13]);          \
    stB_pw(S_ + 2048, gr + 64, 1, p0, pw[14], pw[15]);          \
} while (0)

#define CP_A(STAGE, KTT) do {                                   \
    const uint32_t sA_ = shA + (STAGE) * 16384;                 \
    const uint32_t* src_ = Ptile + (size_t)(KTT) * 4096;        \
    CP_ASYNC16(sA_,             src_);                          \
    CP_ASYNC16(sA_ + 16,        src_ + 4);                      \
    CP_ASYNC16(sA_ + 8192,      src_ + 2048);                   \
    CP_ASYNC16(sA_ + 8192 + 16, src_ + 2048 + 4);               \
    CP_COMMIT();                                                \
} while (0)

    // prologue
    CP_A(0, 0);
    CP_A(1, 1);
    LDG_PACK_B(0); STS_B(Bs3);
    LDG_PACK_B(1); STS_B(Bs3 + 4096);
    LDG_PACK_B(2);
    CP_WAIT1();
    __syncthreads();

#pragma unroll
    for (int ktt = 0; ktt < 8; ktt++) {
        const uint32_t* Ac = As3 + (ktt % 3) * 4096;
        const uint32_t* Bc = Bs3 + (ktt % 3) * 4096;

        if (ktt + 2 < 8) STS_B((uint32_t*)(Bs3 + ((ktt + 2) % 3) * 4096));
        if (ktt + 3 < 8) LDG_PACK_B(ktt + 3);
        if (ktt + 2 < 8) CP_A((ktt + 2) % 3, ktt + 2);

        mma_block(Ac, Bc, 0, wm, wn, physL, acc);
        mma_block(Ac, Bc, 1, wm, wn, physL, acc);
        mma_block(Ac + 2048, Bc + 2048, 0, wm, wn, physL, acc);
        mma_block(Ac + 2048, Bc + 2048, 1, wm, wn, physL, acc);

        if (ktt + 1 < 8) {
            if (ktt + 2 < 8) { CP_WAIT1(); } else { CP_WAIT0(); }
            __syncthreads();
        }
    }
#undef LDG_PACK_B
#undef STS_B
#undef CP_A

    // fused row/col max epilogue with index scatter
    __syncthreads();
    const int lx = lane & 3, ly = lane >> 2;
#pragma unroll
    for (int mt = 0; mt < 4; mt++) {
#pragma unroll
        for (int h = 0; h < 2; h++) {
            float v = NINF;
#pragma unroll
            for (int nt = 0; nt < 4; nt++)
                v = fmaxf(v, fmaxf(acc[mt][nt][2 * h], acc[mt][nt][2 * h + 1]));
            v = fmaxf(v, __shfl_xor_sync(0xffffffffu, v, 1));
            v = fmaxf(v, __shfl_xor_sync(0xffffffffu, v, 2));
            if (lx == 0) atomicMaxF(&s_rmax[wm * 64 + mt * 16 + ly + h * 8], v);
        }
    }
#pragma unroll
    for (int nt = 0; nt < 4; nt++) {
#pragma unroll
        for (int j = 0; j < 2; j++) {
            float v = NINF;
#pragma unroll
            for (int mt = 0; mt < 4; mt++)
                v = fmaxf(v, fmaxf(acc[mt][nt][j], acc[mt][nt][2 + j]));
            v = fmaxf(v, __shfl_xor_sync(0xffffffffu, v, 4));
            v = fmaxf(v, __shfl_xor_sync(0xffffffffu, v, 8));
            v = fmaxf(v, __shfl_xor_sync(0xffffffffu, v, 16));
            if (lane < 4) atomicMaxF(&s_cmax[wn * 32 + nt * 8 + 2 * lane + j], v);
        }
    }
    __syncthreads();
    if (tid < 128) {
        const int jr = l0 + tid;
        if (jr < cnt_t)
            atomicMaxF(&g_rowmax[b * LL + g_idx_t[b * LL + jr]], s_rmax[tid]);
        const int jc = n0 + tid;
        if (jc < cnt_f)
            atomicMaxF(&g_colmax[b * LL + g_idx_f[b * LL + jc]], s_cmax[tid]);
    }
}

// ----------------------------- combine (softmax fused, high-MLP gather) ---------
__global__ void combine_kernel(const float* __restrict__ T,
                               const float* __restrict__ F,
                               float* __restrict__ out)
{
    __shared__ float s_alpha[1024];   // [0:512) alpha_t, [512:1024) alpha_f
    __shared__ float s_red[1024];
    __shared__ int s_it[512];
    __shared__ int s_if[512];
    const int b = blockIdx.y;
    const int tid = threadIdx.x;

    // stage index lists to smem (removes dependent global idx loads from gather)
    if (tid < 512) s_it[tid] = g_idx_t[b * LL + tid];
    else           s_if[tid - 512] = g_idx_f[b * LL + (tid - 512)];

    // --- softmax phase ---
    {
        const bool isF = tid >= 512;
        const int i = tid & 511;
        const float* mx = isF ? (g_colmax + b * LL) : (g_rowmax + b * LL);
        const float* mk = isF ? (g_mf + b * LL) : (g_mt + b * LL);
        const int cnt_other = isF ? g_cnt_t[b] : g_cnt_f[b];

        float mv = mk[i];
        float x = mx[i];
        if (cnt_other < 512) x = fmaxf(x, 0.0f);
        float v = tanhf(x) + (mv - 1.0f) * 1000000.0f;

        s_red[tid] = v;
        __syncthreads();
        for (int s = 256; s > 0; s >>= 1) {
            if ((tid & 511) < s) s_red[tid] = fmaxf(s_red[tid], s_red[tid + s]);
            __syncthreads();
        }
        float vm = s_red[tid & 512];
        __syncthreads();
        float e = expf(v - vm);
        s_red[tid] = e;
        __syncthreads();
        for (int s = 256; s > 0; s >>= 1) {
            if ((tid & 511) < s) s_red[tid] += s_red[tid + s];
            __syncthreads();
        }
        float inv = 1.0f / s_red[tid & 512];
        s_alpha[tid] = e * inv * mv;
    }
    __syncthreads();

    // --- combine phase: 8 independent accumulators, smem indices ---
    const int dl = tid & 127;
    const int chunk = tid >> 7;           // 0..7
    const int d = blockIdx.x * 128 + dl;
    const int ct = g_cnt_t[b], cf = g_cnt_f[b];
    const float* tp = T + (size_t)b * LL * DD + d;
    const float* fp = F + (size_t)b * LL * DD + d;
    const int jb = chunk * 64;

    float a[8];
#pragma unroll
    for (int i = 0; i < 8; i++) a[i] = 0.f;

    {
        const int je = min(jb + 64, ct);
        int j = jb;
        for (; j + 8 <= je; j += 8) {
#pragma unroll
            for (int u = 0; u < 8; u++) {
                int l = s_it[j + u];
                a[u] = fmaf(s_alpha[l], __ldg(tp + (size_t)l * DD), a[u]);
            }
        }
        for (; j < je; j++) {
            int l = s_it[j];
            a[0] = fmaf(s_alpha[l], __ldg(tp + (size_t)l * DD), a[0]);
        }
    }
    {
        const int je = min(jb + 64, cf);
        int j = jb;
        for (; j + 8 <= je; j += 8) {
#pragma unroll
            for (int u = 0; u < 8; u++) {
                int l = s_if[j + u];
                a[u] = fmaf(s_alpha[512 + l], __ldg(fp + (size_t)l * DD), a[u]);
            }
        }
        for (; j < je; j++) {
            int l = s_if[j];
            a[0] = fmaf(s_alpha[512 + l], __ldg(fp + (size_t)l * DD), a[0]);
        }
    }
    s_red[tid] = ((a[0] + a[1]) + (a[2] + a[3])) + ((a[4] + a[5]) + (a[6] + a[7]));
    __syncthreads();
    if (chunk == 0) {
        float s = 0.f;
#pragma unroll
        for (int i = 0; i < 8; i++) s += s_red[dl + 128 * i];
        out[b * DD + d] = s;
    }
}

// ----------------------------- launch -------------------------------------------
extern "C" void kernel_launch(void* const* d_in, const int* in_sizes, int n_in,
                              void* d_out, int out_size)
{
    const float* t  = (const float*)d_in[0];
    const float* f  = (const float*)d_in[1];
    const void*  mt = d_in[2];
    const void*  mf = d_in[3];
    const float* w  = (const float*)d_in[4];
    float* out = (float*)d_out;

    const int GSMEM = 24576 * 4;   // 96 KB dynamic
    cudaFuncSetAttribute(gemm0_kernel, cudaFuncAttributeMaxDynamicSharedMemorySize, GSMEM);
    cudaFuncSetAttribute(gemm1_kernel, cudaFuncAttributeMaxDynamicSharedMemorySize, GSMEM);

    prep_kernel<<<128 + 256, 512>>>(mt, mf, w);
    gemm0_kernel<<<dim3(4, 4, Bb), 256, GSMEM>>>(t);
    gemm1_kernel<<<dim3(4, 4, Bb), 256, GSMEM>>>(f);
    combine_kernel<<<dim3(4, Bb), 1024>>>(t, f, out);
}

// round 17
// speedup vs baseline: 1.5222x; 1.0911x over previous
#include <cuda_runtime.h>
#include <math.h>
#include <stdint.h>

#define Bb 64
#define LL 512
#define DD 512

// ----------------------------- scratch ---------------------------------------
__device__ uint32_t g_projb[(size_t)Bb * 4 * 16 * 2048];  // proj tiles, A-frag order
__device__ uint32_t g_wtb2[4 * 16 * 2048];                // W^T tiles, B-frag order
__device__ float g_mt[Bb * LL];
__device__ float g_mf[Bb * LL];
__device__ int   g_idx_t[Bb * LL];
__device__ int   g_idx_f[Bb * LL];
__device__ int   g_cnt_t[Bb];
__device__ int   g_cnt_f[Bb];
__device__ float g_rowmax[Bb * LL];
__device__ float g_colmax[Bb * LL];

// ----------------------------- helpers ---------------------------------------
__device__ __forceinline__ uint32_t bf16x2_pack(float lo, float hi) {
    uint32_t r;
    asm("cvt.rn.bf16x2.f32 %0, %1, %2;" : "=r"(r) : "f"(hi), "f"(lo));
    return r;
}

__device__ __forceinline__ void mma_bf16(float* c, const uint32_t* a, const uint32_t* b) {
    asm volatile(
        "mma.sync.aligned.m16n8k16.row.col.f32.bf16.bf16.f32 "
        "{%0,%1,%2,%3}, {%4,%5,%6,%7}, {%8,%9}, {%0,%1,%2,%3};\n"
        : "+f"(c[0]), "+f"(c[1]), "+f"(c[2]), "+f"(c[3])
        : "r"(a[0]), "r"(a[1]), "r"(a[2]), "r"(a[3]), "r"(b[0]), "r"(b[1]));
}

#define CP_ASYNC16(sm_u32, gptr) \
    asm volatile("cp.async.cg.shared.global [%0], [%1], 16;" \
                 :: "r"(sm_u32), "l"(gptr) : "memory")
#define CP_COMMIT() asm volatile("cp.async.commit_group;" ::: "memory")
#define CP_WAIT1()  asm volatile("cp.async.wait_group 1;" ::: "memory")
#define CP_WAIT0()  asm volatile("cp.async.wait_group 0;" ::: "memory")

__device__ __forceinline__ void atomicMaxF(float* a, float v) {
    if (v >= 0.0f) atomicMax((int*)a, __float_as_int(v));
    else           atomicMin((unsigned int*)a, __float_as_uint(v));
}

__device__ __forceinline__ float load_mask(const void* p, int i, int fmt) {
    if (fmt == 0) return ((const int*)p)[i] ? 1.0f : 0.0f;
    if (fmt == 1) return ((const float*)p)[i];
    return ((const unsigned char*)p)[i] ? 1.0f : 0.0f;
}

__device__ __forceinline__ float4 zmask(float4 v, bool pred) {
    if (!pred) { v.x = 0.f; v.y = 0.f; v.z = 0.f; v.w = 0.f; }
    return v;
}

__device__ __forceinline__ uint2 pkv(float4 v) {
    uint2 u;
    u.x = bf16x2_pack(v.x, v.y);
    u.y = bf16x2_pack(v.z, v.w);
    return u;
}

// ---- fragment-layout store of pre-packed words (mapping validated R5-R16) ------
__device__ __forceinline__ void stA_pw(uint32_t* dst, int row, int kk, int p0, uint32_t w0, uint32_t w1) {
    const int base = (((row >> 4) * 2 + kk) << 7) + ((row & 15) >> 3);
    const int rl = (row & 7) * 4;
    int lane = rl + (p0 & 3), phys = lane ^ (lane >> 3);
    dst[base + phys * 4 + ((p0 >> 2) << 1)] = w0;
    int p = p0 + 1;
    lane = rl + (p & 3); phys = lane ^ (lane >> 3);
    dst[base + phys * 4 + ((p >> 2) << 1)] = w1;
}

__device__ __forceinline__ void stB_pw(uint32_t* dst, int col, int kk, int p0, uint32_t w0, uint32_t w1) {
    const int base = (((col >> 3) * 2 + kk) << 6);
    const int rl = (col & 7) * 4;
    int lane = rl + (p0 & 3), phys = lane ^ (lane >> 3);
    dst[base + phys * 2 + (p0 >> 2)] = w0;
    int p = p0 + 1;
    lane = rl + (p & 3); phys = lane ^ (lane >> 3);
    dst[base + phys * 2 + (p >> 2)] = w1;
}

// ---- shared MMA block (64x32 warp tile, validated R5-R16) -----------------------
__device__ __forceinline__ void mma_block(const uint32_t* Asb, const uint32_t* Bsb,
                                          int kk, int wm, int wn, int physL,
                                          float acc[4][4][4]) {
    uint4 af[4]; uint2 bfv[4];
#pragma unroll
    for (int mt = 0; mt < 4; mt++)
        af[mt] = *(const uint4*)&Asb[(((wm * 4 + mt) * 2 + kk) << 7) + physL * 4];
#pragma unroll
    for (int nt = 0; nt < 4; nt++)
        bfv[nt] = *(const uint2*)&Bsb[(((wn * 4 + nt) * 2 + kk) << 6) + physL * 2];
#pragma unroll
    for (int mt = 0; mt < 4; mt++)
#pragma unroll
        for (int nt = 0; nt < 4; nt++)
            mma_bf16(acc[mt][nt], (const uint32_t*)&af[mt], (const uint32_t*)&bfv[nt]);
}

// ----------------------------- prep: compact + pack_w ---------------------------
__global__ void prep_kernel(const void* mt, const void* mf, const float* __restrict__ W) {
    const int bx = blockIdx.x;
    const int tid = threadIdx.x;   // 512

    if (bx < 128) {
        __shared__ int s_i32, s_f32;
        __shared__ int wsum[16];
        __shared__ int wbase[16];

        const int b = bx >> 1;
        const bool isF = bx & 1;

        if (tid == 0) { s_i32 = 1; s_f32 = 1; }
        __syncthreads();
        if (tid < 256) {
            unsigned int w = ((const unsigned int*)mt)[tid];
            if (w > 1u) atomicAnd(&s_i32, 0);
            if (w != 0u && w != 0x3F800000u) atomicAnd(&s_f32, 0);
        }
        __syncthreads();
        const int fmt = s_i32 ? 0 : (s_f32 ? 1 : 2);

        const float mv = load_mask(isF ? mf : mt, b * LL + tid, fmt);
        (isF ? g_mf : g_mt)[b * LL + tid] = mv;
        (isF ? g_colmax : g_rowmax)[b * LL + tid] = __int_as_float(0xff800000);

        const bool on = (mv != 0.0f);
        const unsigned bal = __ballot_sync(0xffffffffu, on);
        const int wid = tid >> 5, lane = tid & 31;
        if (lane == 0) wsum[wid] = __popc(bal);
        __syncthreads();
        if (tid == 0) {
            int s = 0;
            for (int i = 0; i < 16; i++) { wbase[i] = s; s += wsum[i]; }
            if (isF) g_cnt_f[b] = s; else g_cnt_t[b] = s;
        }
        __syncthreads();
        if (on) {
            int pos = wbase[wid] + __popc(bal & ((1u << lane) - 1u));
            (isF ? g_idx_f : g_idx_t)[b * LL + pos] = tid;
        }
    } else {
        const int p = bx - 128;     // k-pair 0..255
        const int n = tid;
        const int k0 = p * 2;
        float lo = W[(size_t)k0 * DD + n];
        float hi = W[(size_t)(k0 + 1) * DD + n];
        const int nt = n >> 7, col = n & 127;
        const int kt = p >> 4, kk = (p >> 3) & 1, pl = p & 7;
        const int lane_v = (col & 7) * 4 + (pl & 3);
        const int phys = lane_v ^ (lane_v >> 3);
        const int idx = (nt * 16 + kt) * 2048 +
                        (((col >> 3) * 2 + kk) << 6) + phys * 2 + (pl >> 2);
        g_wtb2[idx] = bf16x2_pack(lo, hi);
    }
}

// ----------------------------- GEMM 0: proj = compact(t) @ W^T ------------------
__global__ void __launch_bounds__(256, 2) gemm0_kernel(const float* __restrict__ T)
{
    extern __shared__ uint32_t dsm[];
    uint32_t* As3 = dsm;              // packed A: 3 stages x 4096 words
    uint32_t* Bs3 = dsm + 12288;      // async  B: 3 stages x 4096 words

    const int tid  = threadIdx.x;
    const int lane = tid & 31;
    const int wid  = tid >> 5;
    const int wm   = wid & 1;
    const int wn   = wid >> 1;
    const int b  = blockIdx.z;
    const int l0 = blockIdx.y * 128;
    const int nt_tile = blockIdx.x;

    const int cnt = g_cnt_t[b];
    if (l0 >= cnt) return;

    const int gr = tid >> 2;
    const int gc = (tid & 3) * 4;
    const int p0 = gc >> 1;
    const int physL = lane ^ (lane >> 3);

    const int j0 = l0 + gr, j1 = l0 + gr + 64;
    const bool pr0 = (j0 < cnt), pr1 = (j1 < cnt);
    const int r0 = pr0 ? g_idx_t[b * LL + j0] : 0;
    const int r1 = pr1 ? g_idx_t[b * LL + j1] : 0;

    const float* Ab0 = T + ((size_t)b * LL + r0) * DD + gc;
    const float* Ab1 = T + ((size_t)b * LL + r1) * DD + gc;
    const uint32_t* Wtile = g_wtb2 + (size_t)nt_tile * 16 * 2048 + tid * 8;

    const uint32_t shB = (uint32_t)__cvta_generic_to_shared(dsm) + 12288 * 4 + tid * 32;

    float acc[4][4][4];
#pragma unroll
    for (int i = 0; i < 4; i++)
#pragma unroll
        for (int j = 0; j < 4; j++)
#pragma unroll
            for (int q = 0; q < 4; q++) acc[i][j][q] = 0.0f;

    uint32_t pw[16];

#define LDG_PACK_A(KTT) do {                                                  \
    const int K0_ = (KTT) * 64;                                               \
    uint2 u_;                                                                 \
    u_ = pkv(zmask(*(const float4*)(Ab0 + K0_), pr0));      pw[0]=u_.x;  pw[1]=u_.y;  \
    u_ = pkv(zmask(*(const float4*)(Ab0 + K0_ + 16), pr0)); pw[2]=u_.x;  pw[3]=u_.y;  \
    u_ = pkv(zmask(*(const float4*)(Ab1 + K0_), pr1));      pw[4]=u_.x;  pw[5]=u_.y;  \
    u_ = pkv(zmask(*(const float4*)(Ab1 + K0_ + 16), pr1)); pw[6]=u_.x;  pw[7]=u_.y;  \
    u_ = pkv(zmask(*(const float4*)(Ab0 + K0_ + 32), pr0)); pw[8]=u_.x;  pw[9]=u_.y;  \
    u_ = pkv(zmask(*(const float4*)(Ab0 + K0_ + 48), pr0)); pw[10]=u_.x; pw[11]=u_.y; \
    u_ = pkv(zmask(*(const float4*)(Ab1 + K0_ + 32), pr1)); pw[12]=u_.x; pw[13]=u_.y; \
    u_ = pkv(zmask(*(const float4*)(Ab1 + K0_ + 48), pr1)); pw[14]=u_.x; pw[15]=u_.y; \
} while (0)

#define STS_A(Sg) do {                                          \
    uint32_t* S_ = (Sg);                                        \
    stA_pw(S_, gr,      0, p0, pw[0],  pw[1]);                  \
    stA_pw(S_, gr,      1, p0, pw[2],  pw[3]);                  \
    stA_pw(S_, gr + 64, 0, p0, pw[4],  pw[5]);                  \
    stA_pw(S_, gr + 64, 1, p0, pw[6],  pw[7]);                  \
    stA_pw(S_ + 2048, gr,      0, p0, pw[8],  pw[9]);           \
    stA_pw(S_ + 2048, gr,      1, p0, pw[10], pw[11]);          \
    stA_pw(S_ + 2048, gr + 64, 0, p0, pw[12], pw[13]);          \
    stA_pw(S_ + 2048, gr + 64, 1, p0, pw[14], pw[15]);          \
} while (0)

#define CP_B(STAGE, KTT) do {                                   \
    const uint32_t sB_ = shB + (STAGE) * 16384;                 \
    const uint32_t* src_ = Wtile + (size_t)(KTT) * 4096;        \
    CP_ASYNC16(sB_,             src_);                          \
    CP_ASYNC16(sB_ + 16,        src_ + 4);                      \
    CP_ASYNC16(sB_ + 8192,      src_ + 2048);                   \
    CP_ASYNC16(sB_ + 8192 + 16, src_ + 2048 + 4);               \
    CP_COMMIT();                                                \
} while (0)

    // prologue
    CP_B(0, 0);
    CP_B(1, 1);
    LDG_PACK_A(0); STS_A(As3);
    LDG_PACK_A(1); STS_A(As3 + 4096);
    LDG_PACK_A(2);
    CP_WAIT1();
    __syncthreads();

#pragma unroll
    for (int ktt = 0; ktt < 8; ktt++) {
        const uint32_t* Ac = As3 + (ktt % 3) * 4096;
        const uint32_t* Bc = Bs3 + (ktt % 3) * 4096;

        if (ktt + 2 < 8) STS_A((uint32_t*)(As3 + ((ktt + 2) % 3) * 4096));
        if (ktt + 3 < 8) LDG_PACK_A(ktt + 3);
        if (ktt + 2 < 8) CP_B((ktt + 2) % 3, ktt + 2);

        mma_block(Ac, Bc, 0, wm, wn, physL, acc);
        mma_block(Ac, Bc, 1, wm, wn, physL, acc);
        mma_block(Ac + 2048, Bc + 2048, 0, wm, wn, physL, acc);
        mma_block(Ac + 2048, Bc + 2048, 1, wm, wn, physL, acc);

        if (ktt + 1 < 8) {
            if (ktt + 2 < 8) { CP_WAIT1(); } else { CP_WAIT0(); }
            __syncthreads();
        }
    }
#undef LDG_PACK_A
#undef STS_A
#undef CP_B

    // epilogue: proj tiles in EXACT mma_block A-fragment layout
    const int lx = lane & 3, ly = lane >> 2;
    uint32_t* Ptile = g_projb + ((size_t)b * 4 + blockIdx.y) * 16 * 2048;
#pragma unroll
    for (int mt = 0; mt < 4; mt++) {
        const int mtile = wm * 4 + mt;
#pragma unroll
        for (int nt = 0; nt < 4; nt++) {
            const int c = nt_tile * 128 + wn * 32 + nt * 8 + 2 * lx;
            const int kp_g = c >> 1;
            const int kt1 = kp_g >> 4;
            const int kk1 = (kp_g >> 3) & 1;
            const int kp  = kp_g & 7;
            const int lane_v = ly * 4 + (kp & 3);
            const int phys = lane_v ^ (lane_v >> 3);
            const int si = (kp >= 4) ? 2 : 0;
            const int idx = kt1 * 2048 + (((mtile * 2 + kk1) << 7)) + phys * 4 + si;
            uint2 w;
            w.x = bf16x2_pack(acc[mt][nt][0], acc[mt][nt][1]);
            w.y = bf16x2_pack(acc[mt][nt][2], acc[mt][nt][3]);
            *(uint2*)&Ptile[idx] = w;
        }
    }
}

// ------------- GEMM 1: M = proj(compact) @ compact(f)^T, fused max --------------
__global__ void __launch_bounds__(256, 2) gemm1_kernel(const float* __restrict__ F)
{
    extern __shared__ uint32_t dsm[];
    uint32_t* As3 = dsm;              // async  A: 3 stages x 4096 words
    uint32_t* Bs3 = dsm + 12288;      // packed B: 3 stages x 4096 words
    __shared__ float s_rmax[128];
    __shared__ float s_cmax[128];

    const int tid  = threadIdx.x;
    const int lane = tid & 31;
    const int wid  = tid >> 5;
    const int wm   = wid & 1;
    const int wn   = wid >> 1;
    const int b  = blockIdx.z;
    const int l0 = blockIdx.y * 128;
    const int n0 = blockIdx.x * 128;

    const int cnt_t = g_cnt_t[b];
    const int cnt_f = g_cnt_f[b];
    if (l0 >= cnt_t || n0 >= cnt_f) return;

    const int gr = tid >> 2;
    const int gc = (tid & 3) * 4;
    const int p0 = gc >> 1;
    const int physL = lane ^ (lane >> 3);
    const float NINF = __int_as_float(0xff800000);

    const int j0 = n0 + gr, j1 = n0 + gr + 64;
    const bool pr0 = (j0 < cnt_f), pr1 = (j1 < cnt_f);
    const int c0 = pr0 ? g_idx_f[b * LL + j0] : 0;
    const int c1 = pr1 ? g_idx_f[b * LL + j1] : 0;

    if (tid < 128) { s_rmax[tid] = NINF; s_cmax[tid] = NINF; }

    const uint32_t* Ptile = g_projb + ((size_t)b * 4 + blockIdx.y) * 16 * 2048 + tid * 8;
    const float* Fb0 = F + ((size_t)b * LL + c0) * DD + gc;
    const float* Fb1 = F + ((size_t)b * LL + c1) * DD + gc;

    const uint32_t shA = (uint32_t)__cvta_generic_to_shared(dsm) + tid * 32;

    float acc[4][4][4];
#pragma unroll
    for (int i = 0; i < 4; i++)
#pragma unroll
        for (int j = 0; j < 4; j++)
#pragma unroll
            for (int q = 0; q < 4; q++) acc[i][j][q] = 0.0f;

    uint32_t pw[16];

#define LDG_PACK_B(KTT) do {                                                  \
    const int K0_ = (KTT) * 64;                                               \
    uint2 u_;                                                                 \
    u_ = pkv(zmask(*(const float4*)(Fb0 + K0_), pr0));      pw[0]=u_.x;  pw[1]=u_.y;  \
    u_ = pkv(zmask(*(const float4*)(Fb0 + K0_ + 16), pr0)); pw[2]=u_.x;  pw[3]=u_.y;  \
    u_ = pkv(zmask(*(const float4*)(Fb1 + K0_), pr1));      pw[4]=u_.x;  pw[5]=u_.y;  \
    u_ = pkv(zmask(*(const float4*)(Fb1 + K0_ + 16), pr1)); pw[6]=u_.x;  pw[7]=u_.y;  \
    u_ = pkv(zmask(*(const float4*)(Fb0 + K0_ + 32), pr0)); pw[8]=u_.x;  pw[9]=u_.y;  \
    u_ = pkv(zmask(*(const float4*)(Fb0 + K0_ + 48), pr0)); pw[10]=u_.x; pw[11]=u_.y; \
    u_ = pkv(zmask(*(const float4*)(Fb1 + K0_ + 32), pr1)); pw[12]=u_.x; pw[13]=u_.y; \
    u_ = pkv(zmask(*(const float4*)(Fb1 + K0_ + 48), pr1)); pw[14]=u_.x; pw[15]=u_.y; \
} while (0)

#define STS_B(Sg) do {                                          \
    uint32_t* S_ = (Sg);                                        \
    stB_pw(S_, gr,      0, p0, pw[0],  pw[1]);                  \
    stB_pw(S_, gr,      1, p0, pw[2],  pw[3]);                  \
    stB_pw(S_, gr + 64, 0, p0, pw[4],  pw[5]);                  \
    stB_pw(S_, gr + 64, 1, p0, pw[6],  pw[7]);                  \
    stB_pw(S_ + 2048, gr,      0, p0, pw[8],  pw[9]);           \
    stB_pw(S_ + 2048, gr,      1, p0, pw[10], pw[11]);          \
    stB_pw(S_ + 2048, gr + 64, 0, p0, pw[12], pw[13]);          \
    stB_pw(S_ + 2048, gr + 64, 1, p0, pw[14], pw[15]);          \
} while (0)

#define CP_A(STAGE, KTT) do {                                   \
    const uint32_t sA_ = shA + (STAGE) * 16384;                 \
    const uint32_t* src_ = Ptile + (size_t)(KTT) * 4096;        \
    CP_ASYNC16(sA_,             src_);                          \
    CP_ASYNC16(sA_ + 16,        src_ + 4);                      \
    CP_ASYNC16(sA_ + 8192,      src_ + 2048);                   \
    CP_ASYNC16(sA_ + 8192 + 16, src_ + 2048 + 4);               \
    CP_COMMIT();                                                \
} while (0)

    // prologue
    CP_A(0, 0);
    CP_A(1, 1);
    LDG_PACK_B(0); STS_B(Bs3);
    LDG_PACK_B(1); STS_B(Bs3 + 4096);
    LDG_PACK_B(2);
    CP_WAIT1();
    __syncthreads();

#pragma unroll
    for (int ktt = 0; ktt < 8; ktt++) {
        const uint32_t* Ac = As3 + (ktt % 3) * 4096;
        const uint32_t* Bc = Bs3 + (ktt % 3) * 4096;

        if (ktt + 2 < 8) STS_B((uint32_t*)(Bs3 + ((ktt + 2) % 3) * 4096));
        if (ktt + 3 < 8) LDG_PACK_B(ktt + 3);
        if (ktt + 2 < 8) CP_A((ktt + 2) % 3, ktt + 2);

        mma_block(Ac, Bc, 0, wm, wn, physL, acc);
        mma_block(Ac, Bc, 1, wm, wn, physL, acc);
        mma_block(Ac + 2048, Bc + 2048, 0, wm, wn, physL, acc);
        mma_block(Ac + 2048, Bc + 2048, 1, wm, wn, physL, acc);

        if (ktt + 1 < 8) {
            if (ktt + 2 < 8) { CP_WAIT1(); } else { CP_WAIT0(); }
            __syncthreads();
        }
    }
#undef LDG_PACK_B
#undef STS_B
#undef CP_A

    // fused row/col max epilogue with index scatter
    __syncthreads();
    const int lx = lane & 3, ly = lane >> 2;
#pragma unroll
    for (int mt = 0; mt < 4; mt++) {
#pragma unroll
        for (int h = 0; h < 2; h++) {
            float v = NINF;
#pragma unroll
            for (int nt = 0; nt < 4; nt++)
                v = fmaxf(v, fmaxf(acc[mt][nt][2 * h], acc[mt][nt][2 * h + 1]));
            v = fmaxf(v, __shfl_xor_sync(0xffffffffu, v, 1));
            v = fmaxf(v, __shfl_xor_sync(0xffffffffu, v, 2));
            if (lx == 0) atomicMaxF(&s_rmax[wm * 64 + mt * 16 + ly + h * 8], v);
        }
    }
#pragma unroll
    for (int nt = 0; nt < 4; nt++) {
#pragma unroll
        for (int j = 0; j < 2; j++) {
            float v = NINF;
#pragma unroll
            for (int mt = 0; mt < 4; mt++)
                v = fmaxf(v, fmaxf(acc[mt][nt][j], acc[mt][nt][2 + j]));
            v = fmaxf(v, __shfl_xor_sync(0xffffffffu, v, 4));
            v = fmaxf(v, __shfl_xor_sync(0xffffffffu, v, 8));
            v = fmaxf(v, __shfl_xor_sync(0xffffffffu, v, 16));
            if (lane < 4) atomicMaxF(&s_cmax[wn * 32 + nt * 8 + 2 * lane + j], v);
        }
    }
    __syncthreads();
    if (tid < 128) {
        const int jr = l0 + tid;
        if (jr < cnt_t)
            atomicMaxF(&g_rowmax[b * LL + g_idx_t[b * LL + jr]], s_rmax[tid]);
        const int jc = n0 + tid;
        if (jc < cnt_f)
            atomicMaxF(&g_colmax[b * LL + g_idx_f[b * LL + jc]], s_cmax[tid]);
    }
}

// ----------------------------- combine (softmax fused, LDG.128 gather) ----------
// grid (4, Bb), block 1024. lane = 4 d-cols (float4), warp = 16-row chunk.
__global__ void combine_kernel(const float* __restrict__ T,
                               const float* __restrict__ F,
                               float* __restrict__ out)
{
    __shared__ float s_alpha[1024];   // [0:512) alpha_t, [512:1024) alpha_f
    __shared__ float s_red[1024];
    __shared__ float4 s_acc[1024];    // 16 KB reduction buffer
    __shared__ int s_it[512];
    __shared__ int s_if[512];
    const int b = blockIdx.y;
    const int tid = threadIdx.x;

    // stage index lists to smem
    if (tid < 512) s_it[tid] = g_idx_t[b * LL + tid];
    else           s_if[tid - 512] = g_idx_f[b * LL + (tid - 512)];

    // --- softmax phase ---
    {
        const bool isF = tid >= 512;
        const int i = tid & 511;
        const float* mx = isF ? (g_colmax + b * LL) : (g_rowmax + b * LL);
        const float* mk = isF ? (g_mf + b * LL) : (g_mt + b * LL);
        const int cnt_other = isF ? g_cnt_t[b] : g_cnt_f[b];

        float mv = mk[i];
        float x = mx[i];
        if (cnt_other < 512) x = fmaxf(x, 0.0f);
        float v = tanhf(x) + (mv - 1.0f) * 1000000.0f;

        s_red[tid] = v;
        __syncthreads();
        for (int s = 256; s > 0; s >>= 1) {
            if ((tid & 511) < s) s_red[tid] = fmaxf(s_red[tid], s_red[tid + s]);
            __syncthreads();
        }
        float vm = s_red[tid & 512];
        __syncthreads();
        float e = expf(v - vm);
        s_red[tid] = e;
        __syncthreads();
        for (int s = 256; s > 0; s >>= 1) {
            if ((tid & 511) < s) s_red[tid] += s_red[tid + s];
            __syncthreads();
        }
        float inv = 1.0f / s_red[tid & 512];
        s_alpha[tid] = e * inv * mv;
    }
    __syncthreads();

    // --- combine phase: float4 gather, 4 independent chains per thread ---
    const int lane = tid & 31;
    const int w = tid >> 5;               // 0..31, 16-row chunk owner
    const int d4 = blockIdx.x * 128 + lane * 4;
    const int ct = g_cnt_t[b], cf = g_cnt_f[b];
    const float* tp = T + (size_t)b * LL * DD + d4;
    const float* fp = F + (size_t)b * LL * DD + d4;
    const int jb = w * 16;

    float4 a0 = {0,0,0,0}, a1 = {0,0,0,0}, a2 = {0,0,0,0}, a3 = {0,0,0,0};

#define GACC(ACC, AL, V) do {                       \
    float4 v_ = (V); float al_ = (AL);              \
    ACC.x = fmaf(al_, v_.x, ACC.x);                 \
    ACC.y = fmaf(al_, v_.y, ACC.y);                 \
    ACC.z = fmaf(al_, v_.z, ACC.z);                 \
    ACC.w = fmaf(al_, v_.w, ACC.w);                 \
} while (0)

    {
        const int je = min(jb + 16, ct);
        int j = jb;
        for (; j + 4 <= je; j += 4) {
            int l0 = s_it[j], l1 = s_it[j + 1], l2 = s_it[j + 2], l3 = s_it[j + 3];
            GACC(a0, s_alpha[l0], __ldg((const float4*)(tp + (size_t)l0 * DD)));
            GACC(a1, s_alpha[l1], __ldg((const float4*)(tp + (size_t)l1 * DD)));
            GACC(a2, s_alpha[l2], __ldg((const float4*)(tp + (size_t)l2 * DD)));
            GACC(a3, s_alpha[l3], __ldg((const float4*)(tp + (size_t)l3 * DD)));
        }
        for (; j < je; j++) {
            int l = s_it[j];
            GACC(a0, s_alpha[l], __ldg((const float4*)(tp + (size_t)l * DD)));
        }
    }
    {
        const int je = min(jb + 16, cf);
        int j = jb;
        for (; j + 4 <= je; j += 4) {
            int l0 = s_if[j], l1 = s_if[j + 1], l2 = s_if[j + 2], l3 = s_if[j + 3];
            GACC(a0, s_alpha[512 + l0], __ldg((const float4*)(fp + (size_t)l0 * DD)));
            GACC(a1, s_alpha[512 + l1], __ldg((const float4*)(fp + (size_t)l1 * DD)));
            GACC(a2, s_alpha[512 + l2], __ldg((const float4*)(fp + (size_t)l2 * DD)));
            GACC(a3, s_alpha[512 + l3], __ldg((const float4*)(fp + (size_t)l3 * DD)));
        }
        for (; j < je; j++) {
            int l = s_if[j];
            GACC(a0, s_alpha[512 + l], __ldg((const float4*)(fp + (size_t)l * DD)));
        }
    }
#undef GACC

    float4 at;
    at.x = (a0.x + a1.x) + (a2.x + a3.x);
    at.y = (a0.y + a1.y) + (a2.y + a3.y);
    at.z = (a0.z + a1.z) + (a2.z + a3.z);
    at.w = (a0.w + a1.w) + (a2.w + a3.w);
    s_acc[tid] = at;
    __syncthreads();

    // tree-reduce over the 32 warps
    for (int s = 16; s > 0; s >>= 1) {
        if (w < s) {
            float4 o = s_acc[(w + s) * 32 + lane];
            float4 m = s_acc[tid];
            m.x += o.x; m.y += o.y; m.z += o.z; m.w += o.w;
            s_acc[tid] = m;
        }
        __syncthreads();
    }
    if (w == 0)
        *(float4*)(out + b * DD + d4) = s_acc[lane];
}

// ----------------------------- launch -------------------------------------------
extern "C" void kernel_launch(void* const* d_in, const int* in_sizes, int n_in,
                              void* d_out, int out_size)
{
    const float* t  = (const float*)d_in[0];
    const float* f  = (const float*)d_in[1];
    const void*  mt = d_in[2];
    const void*  mf = d_in[3];
    const float* w  = (const float*)d_in[4];
    float* out = (float*)d_out;

    const int GSMEM = 24576 * 4;   // 96 KB dynamic
    cudaFuncSetAttribute(gemm0_kernel, cudaFuncAttributeMaxDynamicSharedMemorySize, GSMEM);
    cudaFuncSetAttribute(gemm1_kernel, cudaFuncAttributeMaxDynamicSharedMemorySize, GSMEM);

    prep_kernel<<<128 + 256, 512>>>(mt, mf, w);
    gemm0_kernel<<<dim3(4, 4, Bb), 256, GSMEM>>>(t);
    gemm1_kernel<<<dim3(4, 4, Bb), 256, GSMEM>>>(f);
    combine_kernel<<<dim3(4, Bb), 1024>>>(t, f, out);
}